// round 10
// baseline (speedup 1.0000x reference)
#include <cuda_runtime.h>
#include <cstdint>
#include <cstddef>

// ---------------- problem constants ----------------
#define DIMD   2048
#define MTOT   16384            // 4*4096 tokens
#define N1     6144             // 3*DIMD
#define KD     2048
#define SEQ    4096

// ---------------- scratch (k-permuted layouts for GEMM operands) ----------
// Within each 16-element k-group, position 4j+i holds k = j + 4i:
// order [0,4,8,12, 1,5,9,13, 2,6,10,14, 3,7,11,15]. A thread's float4 at
// position 4*tig = {k=tig, tig+4, tig+8, tig+12} -> fragments for TWO
// ks-steps in one LDS.128.
__device__ float g_xn[(size_t)MTOT * KD];
__device__ float g_h [(size_t)MTOT * N1];
__device__ float g_o [(size_t)MTOT * KD];
__device__ float g_We[(size_t)N1  * KD];
__device__ float g_Wp[(size_t)KD  * KD];

// ---------------- helpers ----------------
__device__ __forceinline__ float to_tf32(float x) {
    float r; asm("cvt.rna.tf32.f32 %0, %1;" : "=f"(r) : "f"(x)); return r;
}
__device__ __forceinline__ void cpasync16(void* smem, const void* gmem) {
    uint32_t s = (uint32_t)__cvta_generic_to_shared(smem);
    asm volatile("cp.async.cg.shared.global [%0], [%1], 16;" :: "r"(s), "l"(gmem));
}
#define CP_COMMIT() asm volatile("cp.async.commit_group;")
#define CP_WAIT1()  asm volatile("cp.async.wait_group 1;")

__device__ __forceinline__ uint4 lds128(uint32_t a) {
    uint4 v;
    asm volatile("ld.shared.v4.b32 {%0,%1,%2,%3}, [%4];"
                 : "=r"(v.x), "=r"(v.y), "=r"(v.z), "=r"(v.w) : "r"(a));
    return v;
}

__device__ __forceinline__ void mma_tf32(float c[4], uint32_t a0, uint32_t a1,
                                         uint32_t a2, uint32_t a3,
                                         uint32_t b0, uint32_t b1) {
    asm volatile(
        "mma.sync.aligned.m16n8k8.row.col.f32.tf32.tf32.f32 "
        "{%0,%1,%2,%3}, {%4,%5,%6,%7}, {%8,%9}, {%0,%1,%2,%3};"
        : "+f"(c[0]), "+f"(c[1]), "+f"(c[2]), "+f"(c[3])
        : "r"(a0), "r"(a1), "r"(a2), "r"(a3), "r"(b0), "r"(b1));
}

// ---------------- tf32 GEMM v10: C[M,N] = A[M,K] * B[N,K]^T ----------------
// CTA 128x256, 8 warps (2Mx4N), warp tile 64x64, BK=32, NSTG=3.
// 128B smem rows, XOR swizzle key(row)=((row&1)<<2)|((row>>1)&3) on 16B
// chunks -> conflict-free LDS.128 fragment loads AND conflict-free cp.async.
// Per ks-pair: 16 LDS.128 feed 128 MMAs (8 LDS.128 per ks vs 16 LDS.64 in v9).
constexpr int BM = 128, BN = 256, BK = 32, NSTG = 3;
constexpr int ROW_F = 32;                            // floats per smem row
constexpr int A_FLOATS = BM * ROW_F;                 // 4096
constexpr int B_FLOATS = BN * ROW_F;                 // 8192
constexpr int STG_FLOATS = A_FLOATS + B_FLOATS;      // 12288
constexpr int STG_BYTES  = STG_FLOATS * 4;           // 49152
constexpr int SMEM_SZ = NSTG * STG_BYTES;            // 147456 B

template<int N, bool FUSE>
__global__ void __launch_bounds__(256, 1) gemm_k(const float* __restrict__ A,
                                                 const float* __restrict__ B,
                                                 float* __restrict__ C,
                                                 const float* __restrict__ xres,
                                                 const float* __restrict__ cs) {
    constexpr int K = KD;
    constexpr int KT = K / BK;    // 64
    extern __shared__ float smem[];
    const uint32_t sbase = (uint32_t)__cvta_generic_to_shared(smem);

    const int bm = blockIdx.y * BM;
    const int bn = blockIdx.x * BN;
    const int tid  = threadIdx.x;
    const int warp = tid >> 5, lane = tid & 31;
    const int wm = (warp & 1) * 64;
    const int wn = (warp >> 1) * 64;
    const int gid = lane >> 2, tig = lane & 3;

    float acc[4][8][4];
    #pragma unroll
    for (int mi = 0; mi < 4; mi++)
        #pragma unroll
        for (int ni = 0; ni < 8; ni++)
            #pragma unroll
            for (int r = 0; r < 4; r++) acc[mi][ni][r] = 0.f;

    const float* Abase = A + (size_t)bm * K;
    const float* Bbase = B + (size_t)bn * K;

    auto load_stage = [&](int kt) {
        float* sa = smem + (kt % NSTG) * STG_FLOATS;
        float* sb = sa + A_FLOATS;
        const float* Ag = Abase + kt * BK;
        const float* Bg = Bbase + kt * BK;
        #pragma unroll
        for (int i = 0; i < 4; i++) {
            int c = tid + i * 256;
            int row = c >> 3, ck = c & 7;
            int key = ((row & 1) << 2) | ((row >> 1) & 3);
            cpasync16(sa + row * ROW_F + ((ck ^ key) << 2),
                      Ag + (size_t)row * K + ck * 4);
        }
        #pragma unroll
        for (int i = 0; i < 8; i++) {
            int c = tid + i * 256;
            int row = c >> 3, ck = c & 7;
            int key = ((row & 1) << 2) | ((row >> 1) & 3);
            cpasync16(sb + row * ROW_F + ((ck ^ key) << 2),
                      Bg + (size_t)row * K + ck * 4);
        }
    };

    // per-thread invariants (bytes)
    const uint32_t key = (uint32_t)(((gid & 1) << 2) | ((gid >> 1) & 3));
    // column byte offset within row for super-step sp: ((sp*4+tig)^key)*16
    const uint32_t colb0 = (uint32_t)((tig ^ key) << 4);
    const uint32_t colb1 = (uint32_t)(((4 | tig) ^ key) << 4);
    const uint32_t arow = (uint32_t)(wm + gid) * 128;
    const uint32_t brow = (uint32_t)(A_FLOATS * 4) + (uint32_t)(wn + gid) * 128;

    uint4 fa[4][2];   // [mi][row-half], each = frags for 2 ks
    uint4 fb[8];      // [ni]

    auto load_frags = [&](uint32_t baseA, uint32_t baseB) {
        #pragma unroll
        for (int ni = 0; ni < 8; ni++)
            fb[ni] = lds128(baseB + (uint32_t)(ni * 8 * 128));
        #pragma unroll
        for (int mi = 0; mi < 4; mi++) {
            fa[mi][0] = lds128(baseA + (uint32_t)(mi * 16 * 128));
            fa[mi][1] = lds128(baseA + (uint32_t)(mi * 16 * 128 + 8 * 128));
        }
    };

    auto mma_pair = [&]() {
        #pragma unroll
        for (int mi = 0; mi < 4; mi++)
            #pragma unroll
            for (int ni = 0; ni < 8; ni++) {
                mma_tf32(acc[mi][ni], fa[mi][0].x, fa[mi][1].x,
                                     fa[mi][0].y, fa[mi][1].y,
                                     fb[ni].x, fb[ni].y);
                mma_tf32(acc[mi][ni], fa[mi][0].z, fa[mi][1].z,
                                     fa[mi][0].w, fa[mi][1].w,
                                     fb[ni].z, fb[ni].w);
            }
    };

    // prologue: 2 stages in flight
    load_stage(0); CP_COMMIT();
    load_stage(1); CP_COMMIT();
    CP_WAIT1();
    __syncthreads();

    #pragma unroll 1
    for (int kt = 0; kt < KT; kt++) {
        const uint32_t stg = sbase + (uint32_t)(kt % NSTG) * STG_BYTES;
        const uint32_t a0 = stg + arow;
        const uint32_t b0 = stg + brow;

        // super-step 0 (ks 0,1)
        load_frags(a0 + colb0, b0 + colb0);
        if (kt + 2 < KT) load_stage(kt + 2);
        CP_COMMIT();
        mma_pair();
        // super-step 1 (ks 2,3)
        load_frags(a0 + colb1, b0 + colb1);
        mma_pair();

        if (kt + 1 < KT) {
            CP_WAIT1();
            __syncthreads();
        }
    }

    // epilogue
    #pragma unroll
    for (int mi = 0; mi < 4; mi++) {
        #pragma unroll
        for (int ni = 0; ni < 8; ni++) {
            int r0 = bm + wm + mi * 16 + gid;
            int c0 = bn + wn + ni * 8 + tig * 2;
            #pragma unroll
            for (int h = 0; h < 2; h++) {
                int r = r0 + h * 8;
                size_t off = (size_t)r * N + c0;
                float v0 = acc[mi][ni][2 * h + 0];
                float v1 = acc[mi][ni][2 * h + 1];
                if (FUSE) {
                    v0 = xres[off]     + cs[c0]     * v0;
                    v1 = xres[off + 1] + cs[c0 + 1] * v1;
                }
                float2 st; st.x = v0; st.y = v1;
                *(float2*)(C + off) = st;
            }
        }
    }
}

// ---------------- prep: round weights to tf32 + 16-wide k-permute --------
template<size_t TOTAL>
__global__ void round_perm_k(const float* __restrict__ src, float* __restrict__ dst) {
    size_t i = (size_t)blockIdx.x * blockDim.x + threadIdx.x;   // 16-group idx
    if (i >= TOTAL / 16) return;
    const float4* s = (const float4*)src + 4 * i;
    float4 a = s[0], b = s[1], c = s[2], d = s[3];
    a.x = to_tf32(a.x); a.y = to_tf32(a.y); a.z = to_tf32(a.z); a.w = to_tf32(a.w);
    b.x = to_tf32(b.x); b.y = to_tf32(b.y); b.z = to_tf32(b.z); b.w = to_tf32(b.w);
    c.x = to_tf32(c.x); c.y = to_tf32(c.y); c.z = to_tf32(c.z); c.w = to_tf32(c.w);
    d.x = to_tf32(d.x); d.y = to_tf32(d.y); d.z = to_tf32(d.z); d.w = to_tf32(d.w);
    float4* o = (float4*)dst + 4 * i;
    o[0] = make_float4(a.x, b.x, c.x, d.x);
    o[1] = make_float4(a.y, b.y, c.y, d.y);
    o[2] = make_float4(a.z, b.z, c.z, d.z);
    o[3] = make_float4(a.w, b.w, c.w, d.w);
}

// ---------------- rmsnorm (emits 16-wide k-permuted tf32 rows) -----------
__global__ void __launch_bounds__(256) rmsnorm_k(const float* __restrict__ x) {
    int row = blockIdx.x;
    const float4* xr = (const float4*)(x + (size_t)row * DIMD);
    int t = threadIdx.x;    // thread t owns k = 8t..8t+7 (half of 16-group t>>1)

    float4 a = xr[2 * t];
    float4 b = xr[2 * t + 1];
    float ss = a.x*a.x + a.y*a.y + a.z*a.z + a.w*a.w
             + b.x*b.x + b.y*b.y + b.z*b.z + b.w*b.w;
    #pragma unroll
    for (int off = 16; off > 0; off >>= 1)
        ss += __shfl_xor_sync(0xffffffffu, ss, off);

    __shared__ float red[8];
    __shared__ float sscale;
    int warp = t >> 5, lane = t & 31;
    if (lane == 0) red[warp] = ss;
    __syncthreads();
    if (t == 0) {
        float tot = 0.f;
        #pragma unroll
        for (int i = 0; i < 8; i++) tot += red[i];
        sscale = rsqrtf(tot * (1.0f / DIMD) + 1.1920928955078125e-07f);
    }
    __syncthreads();
    float sc = sscale;

    float va[4] = {a.x, a.y, a.z, a.w};
    float vb[4] = {b.x, b.y, b.z, b.w};
    // half h=t&1: a[j]=k_{8h+j}, b[j]=k_{8h+j+4} -> pair at pos 4j + 2h
    float* og = g_xn + (size_t)row * DIMD + 16 * (t >> 1) + (t & 1) * 2;
    #pragma unroll
    for (int j = 0; j < 4; j++) {
        float2 p;
        p.x = to_tf32(va[j] * sc);
        p.y = to_tf32(vb[j] * sc);
        *(float2*)(og + 4 * j) = p;
    }
}

// ---------------- gate * causal dwconv * gate (emits permuted o) ---------
// Thread handles channels {d, d+4, d+8, d+12}, d = 16*gg + j -> one float4
// store at permuted positions 16*gg + 4j .. +3.
__global__ void __launch_bounds__(256) gateconv_k(const float* __restrict__ cw,
                                                  const float* __restrict__ cb,
                                                  const int* __restrict__ dil_p) {
    int dil = *dil_p;
    size_t idx = (size_t)blockIdx.x * blockDim.x + threadIdx.x;
    if (idx >= (size_t)MTOT * (DIMD / 4)) return;
    int r = (int)(idx % (DIMD / 4));
    int m = (int)(idx / (DIMD / 4));
    int s = m % SEQ;
    int gg = r >> 2, j = r & 3;
    int dbase = gg * 16 + j;

    const float* hr = g_h + (size_t)m * N1;
    const float* hp1 = hr - (size_t)dil * N1;
    const float* hp2 = hr - (size_t)(2 * dil) * N1;
    bool ok1 = (s >= dil), ok2 = (s >= 2 * dil);

    float o[4];
    #pragma unroll
    for (int i = 0; i < 4; i++) {
        int d = dbase + 4 * i;
        float w0 = cw[d * 3 + 0], w1 = cw[d * 3 + 1], w2 = cw[d * 3 + 2];
        float acc = cb[d] + w2 * (hr[d] * hr[2 * DIMD + d]);
        if (ok1) acc += w1 * (hp1[d] * hp1[2 * DIMD + d]);
        if (ok2) acc += w0 * (hp2[d] * hp2[2 * DIMD + d]);
        o[i] = to_tf32(hr[DIMD + d] * acc);
    }
    float4 st; st.x = o[0]; st.y = o[1]; st.z = o[2]; st.w = o[3];
    *(float4*)(g_o + (size_t)m * DIMD + gg * 16 + 4 * j) = st;
}

// ---------------- launch ----------------
extern "C" void kernel_launch(void* const* d_in, const int* in_sizes, int n_in,
                              void* d_out, int out_size) {
    const float* x   = (const float*)d_in[0];
    const float* We  = (const float*)d_in[1];
    const float* cw  = (const float*)d_in[2];
    const float* cb  = (const float*)d_in[3];
    const float* Wp  = (const float*)d_in[4];
    const float* cs  = (const float*)d_in[5];
    const int*   dil = (const int*)  d_in[6];
    float* out = (float*)d_out;

    float *p_xn, *p_h, *p_o, *p_We, *p_Wp;
    cudaGetSymbolAddress((void**)&p_xn, g_xn);
    cudaGetSymbolAddress((void**)&p_h,  g_h);
    cudaGetSymbolAddress((void**)&p_o,  g_o);
    cudaGetSymbolAddress((void**)&p_We, g_We);
    cudaGetSymbolAddress((void**)&p_Wp, g_Wp);

    cudaFuncSetAttribute(gemm_k<N1, false>, cudaFuncAttributeMaxDynamicSharedMemorySize, SMEM_SZ);
    cudaFuncSetAttribute(gemm_k<KD, true >, cudaFuncAttributeMaxDynamicSharedMemorySize, SMEM_SZ);

    {
        constexpr size_t TWE = (size_t)N1 * KD;
        constexpr size_t TWP = (size_t)KD * KD;
        round_perm_k<TWE><<<(unsigned)((TWE / 16 + 255) / 256), 256>>>(We, p_We);
        round_perm_k<TWP><<<(unsigned)((TWP / 16 + 255) / 256), 256>>>(Wp, p_Wp);
    }

    rmsnorm_k<<<MTOT, 256>>>(x);

    // h = xn @ We^T   [16384 x 6144]
    gemm_k<N1, false><<<dim3(N1 / BN, MTOT / BM), 256, SMEM_SZ>>>(p_xn, p_We, p_h, nullptr, nullptr);

    {
        size_t n = (size_t)MTOT * (DIMD / 4);
        gateconv_k<<<(unsigned)((n + 255) / 256), 256>>>(cw, cb, dil);
    }

    // out = x + cs * (o @ Wp^T)   [16384 x 2048]
    gemm_k<KD, true><<<dim3(KD / BN, MTOT / BM), 256, SMEM_SZ>>>(p_o, p_Wp, out, x, cs);
}

// round 11
// speedup vs baseline: 1.3548x; 1.3548x over previous
#include <cuda_runtime.h>
#include <cstdint>
#include <cstddef>

// ---------------- problem constants ----------------
#define DIMD   2048
#define MTOT   16384            // 4*4096 tokens
#define N1     6144             // 3*DIMD
#define KD     2048
#define SEQ    4096

// ---------------- scratch ----------------
// A operands (g_xn, g_o): 16-wide k-perm, pos 4j+i holds k=j+4i.
// B operands (g_We, g_Wp): 8-wide k-perm, pos 2j+i holds k=j+4i.
__device__ float g_xn[(size_t)MTOT * KD];
__device__ float g_h [(size_t)MTOT * N1];
__device__ float g_o [(size_t)MTOT * KD];
__device__ float g_We[(size_t)N1  * KD];
__device__ float g_Wp[(size_t)KD  * KD];

// ---------------- helpers ----------------
__device__ __forceinline__ float to_tf32(float x) {
    float r; asm("cvt.rna.tf32.f32 %0, %1;" : "=f"(r) : "f"(x)); return r;
}
__device__ __forceinline__ void cpasync16(void* smem, const void* gmem) {
    uint32_t s = (uint32_t)__cvta_generic_to_shared(smem);
    asm volatile("cp.async.cg.shared.global [%0], [%1], 16;" :: "r"(s), "l"(gmem));
}
#define CP_COMMIT() asm volatile("cp.async.commit_group;")
#define CP_WAIT1()  asm volatile("cp.async.wait_group 1;")

__device__ __forceinline__ uint2 lds64(uint32_t a) {
    uint2 v;
    asm volatile("ld.shared.v2.b32 {%0,%1}, [%2];" : "=r"(v.x), "=r"(v.y) : "r"(a));
    return v;
}
__device__ __forceinline__ uint4 lds128(uint32_t a) {
    uint4 v;
    asm volatile("ld.shared.v4.b32 {%0,%1,%2,%3}, [%4];"
                 : "=r"(v.x), "=r"(v.y), "=r"(v.z), "=r"(v.w) : "r"(a));
    return v;
}

__device__ __forceinline__ void mma_tf32(float c[4], uint32_t a0, uint32_t a1,
                                         uint32_t a2, uint32_t a3,
                                         uint32_t b0, uint32_t b1) {
    asm volatile(
        "mma.sync.aligned.m16n8k8.row.col.f32.tf32.tf32.f32 "
        "{%0,%1,%2,%3}, {%4,%5,%6,%7}, {%8,%9}, {%0,%1,%2,%3};"
        : "+f"(c[0]), "+f"(c[1]), "+f"(c[2]), "+f"(c[3])
        : "r"(a0), "r"(a1), "r"(a2), "r"(a3), "r"(b0), "r"(b1));
}

// interleave 8 consecutive-k floats into 8-perm order [0,4,1,5,2,6,3,7]
__device__ __forceinline__ void perm_store8(float* dst, float4 a, float4 b) {
    float4 o0, o1;
    o0.x = a.x; o0.y = b.x; o0.z = a.y; o0.w = b.y;
    o1.x = a.z; o1.y = b.z; o1.z = a.w; o1.w = b.w;
    ((float4*)dst)[0] = o0;
    ((float4*)dst)[1] = o1;
}

// ---------------- tf32 GEMM v11: C[M,N] = A[M,K] * B[N,K]^T ----------------
// CTA 128x256, 8 warps (2Mx4N), warp tile 64x64, BK=32, NSTG=3.
// A: keyA(row)=((row&1)<<2)|((row>>1)&3) swizzle -> conflict-free LDS.128,
//    one load covers 2 ks (16-perm). Single-buffered, reloaded per-mi right
//    after the last consuming MMA (WAR-safe, interleaved).
// B: keyB(row)=(row&3)<<1 swizzle -> conflict-free LDS.64, ping-pong per ks.
constexpr int BM = 128, BN = 256, BK = 32, NSTG = 3;
constexpr int ROW_F = 32;                            // floats per smem row
constexpr int A_FLOATS = BM * ROW_F;                 // 4096
constexpr int B_FLOATS = BN * ROW_F;                 // 8192
constexpr int STG_FLOATS = A_FLOATS + B_FLOATS;      // 12288
constexpr int STG_BYTES  = STG_FLOATS * 4;           // 49152
constexpr int SMEM_SZ = NSTG * STG_BYTES;            // 147456 B

template<int N, bool FUSE>
__global__ void __launch_bounds__(256, 1) gemm_k(const float* __restrict__ A,
                                                 const float* __restrict__ B,
                                                 float* __restrict__ C,
                                                 const float* __restrict__ xres,
                                                 const float* __restrict__ cs) {
    constexpr int K = KD;
    constexpr int KT = K / BK;    // 64
    extern __shared__ float smem[];
    const uint32_t sbase = (uint32_t)__cvta_generic_to_shared(smem);

    const int bm = blockIdx.y * BM;
    const int bn = blockIdx.x * BN;
    const int tid  = threadIdx.x;
    const int warp = tid >> 5, lane = tid & 31;
    const int wm = (warp & 1) * 64;
    const int wn = (warp >> 1) * 64;
    const int gid = lane >> 2, tig = lane & 3;

    float acc[4][8][4];
    #pragma unroll
    for (int mi = 0; mi < 4; mi++)
        #pragma unroll
        for (int ni = 0; ni < 8; ni++)
            #pragma unroll
            for (int r = 0; r < 4; r++) acc[mi][ni][r] = 0.f;

    const float* Abase = A + (size_t)bm * K;
    const float* Bbase = B + (size_t)bn * K;

    auto load_stage = [&](int kt) {
        float* sa = smem + (kt % NSTG) * STG_FLOATS;
        float* sb = sa + A_FLOATS;
        const float* Ag = Abase + kt * BK;
        const float* Bg = Bbase + kt * BK;
        #pragma unroll
        for (int i = 0; i < 4; i++) {
            int c = tid + i * 256;
            int row = c >> 3, ck = c & 7;
            int key = ((row & 1) << 2) | ((row >> 1) & 3);
            cpasync16(sa + row * ROW_F + ((ck ^ key) << 2),
                      Ag + (size_t)row * K + ck * 4);
        }
        #pragma unroll
        for (int i = 0; i < 8; i++) {
            int c = tid + i * 256;
            int row = c >> 3, ck = c & 7;
            int key = (row & 3) << 1;
            cpasync16(sb + row * ROW_F + ((ck ^ key) << 2),
                      Bg + (size_t)row * K + ck * 4);
        }
    };

    uint4    fa[4][2];       // [mi][row-half]; one super-step (2 ks)
    uint32_t fb[2][8][2];    // ping-pong per ks

    // per-thread invariants (bytes)
    const uint32_t keyA = (uint32_t)(((gid & 1) << 2) | ((gid >> 1) & 3));
    const uint32_t keyB = (uint32_t)((gid & 3) << 1);
    const uint32_t tighi = (uint32_t)(tig >> 1);
    const uint32_t tiglo8 = (uint32_t)(tig & 1) * 8;
    const uint32_t colA0 = (uint32_t)((tig ^ keyA) << 4);
    const uint32_t colA1 = (uint32_t)(((4 | tig) ^ keyA) << 4);
    uint32_t colB[4];
    #pragma unroll
    for (int ks = 0; ks < 4; ks++)
        colB[ks] = (((2u * ks + tighi) ^ keyB) << 4) + tiglo8;
    const uint32_t arow = (uint32_t)(wm + gid) * 128;
    const uint32_t brow = (uint32_t)(A_FLOATS * 4) + (uint32_t)(wn + gid) * 128;

    auto ldfa = [&](int mi, uint32_t base) {
        fa[mi][0] = lds128(base + (uint32_t)(mi * 2048));
        fa[mi][1] = lds128(base + (uint32_t)(mi * 2048 + 1024));
    };
    auto ldfb = [&](int buf, int ni, uint32_t base) {
        uint2 u = lds64(base + (uint32_t)(ni * 1024));
        fb[buf][ni][0] = u.x; fb[buf][ni][1] = u.y;
    };
    auto mma8 = [&](int mi, int h, int buf) {
        uint32_t a0 = h ? fa[mi][0].z : fa[mi][0].x;
        uint32_t a1 = h ? fa[mi][1].z : fa[mi][1].x;
        uint32_t a2 = h ? fa[mi][0].w : fa[mi][0].y;
        uint32_t a3 = h ? fa[mi][1].w : fa[mi][1].y;
        #pragma unroll
        for (int ni = 0; ni < 8; ni++)
            mma_tf32(acc[mi][ni], a0, a1, a2, a3, fb[buf][ni][0], fb[buf][ni][1]);
    };

    // prologue: 2 stages in flight, then fa(sp0) + fb0(ks0) of stage 0
    load_stage(0); CP_COMMIT();
    load_stage(1); CP_COMMIT();
    CP_WAIT1();
    __syncthreads();
    {
        const uint32_t aB = sbase + arow + colA0;
        const uint32_t bB = sbase + brow + colB[0];
        #pragma unroll
        for (int mi = 0; mi < 4; mi++) ldfa(mi, aB);
        #pragma unroll
        for (int ni = 0; ni < 8; ni++) ldfb(0, ni, bB);
    }

    #pragma unroll 1
    for (int kt = 0; kt < KT; kt++) {
        const uint32_t stg = sbase + (uint32_t)(kt % NSTG) * STG_BYTES;
        const uint32_t aS = stg + arow;
        const uint32_t bS = stg + brow;

        // ks0: mma(sp0 lo, fb0) + load fb1<-ks1
        #pragma unroll
        for (int mi = 0; mi < 4; mi++) {
            ldfb(1, 2 * mi,     bS + colB[1]);
            ldfb(1, 2 * mi + 1, bS + colB[1]);
            mma8(mi, 0, 0);
        }
        if (kt + 2 < KT) load_stage(kt + 2);
        CP_COMMIT();

        // ks1: mma(sp0 hi, fb1) + load fb0<-ks2 + reload fa[mi]<-sp1 after use
        #pragma unroll
        for (int mi = 0; mi < 4; mi++) {
            ldfb(0, 2 * mi,     bS + colB[2]);
            ldfb(0, 2 * mi + 1, bS + colB[2]);
            mma8(mi, 1, 1);
            ldfa(mi, aS + colA1);
        }

        // ks2: mma(sp1 lo, fb0) + load fb1<-ks3
        #pragma unroll
        for (int mi = 0; mi < 4; mi++) {
            ldfb(1, 2 * mi,     bS + colB[3]);
            ldfb(1, 2 * mi + 1, bS + colB[3]);
            mma8(mi, 0, 0);
        }

        // ks3: mma(sp1 hi, fb1) + prefetch next tile (fa sp0, fb0 ks0)
        if (kt + 1 < KT) {
            CP_WAIT1();
            __syncthreads();
            const uint32_t nstg = sbase + (uint32_t)((kt + 1) % NSTG) * STG_BYTES;
            const uint32_t naB = nstg + arow + colA0;
            const uint32_t nbB = nstg + brow + colB[0];
            #pragma unroll
            for (int mi = 0; mi < 4; mi++) {
                mma8(mi, 1, 1);
                ldfa(mi, naB);
                ldfb(0, 2 * mi,     nbB);
                ldfb(0, 2 * mi + 1, nbB);
            }
        } else {
            #pragma unroll
            for (int mi = 0; mi < 4; mi++) mma8(mi, 1, 1);
        }
    }

    // epilogue
    #pragma unroll
    for (int mi = 0; mi < 4; mi++) {
        #pragma unroll
        for (int ni = 0; ni < 8; ni++) {
            int r0 = bm + wm + mi * 16 + gid;
            int c0 = bn + wn + ni * 8 + tig * 2;
            #pragma unroll
            for (int h = 0; h < 2; h++) {
                int r = r0 + h * 8;
                size_t off = (size_t)r * N + c0;
                float v0 = acc[mi][ni][2 * h + 0];
                float v1 = acc[mi][ni][2 * h + 1];
                if (FUSE) {
                    v0 = xres[off]     + cs[c0]     * v0;
                    v1 = xres[off + 1] + cs[c0 + 1] * v1;
                }
                float2 st; st.x = v0; st.y = v1;
                *(float2*)(C + off) = st;
            }
        }
    }
}

// ---------------- prep: round weights to tf32 + 8-wide k-permute (B ops) --
template<size_t TOTAL>
__global__ void round_perm_k(const float* __restrict__ src, float* __restrict__ dst) {
    size_t i = (size_t)blockIdx.x * blockDim.x + threadIdx.x;   // 8-group index
    if (i >= TOTAL / 8) return;
    float4 a = ((const float4*)src)[2 * i];
    float4 b = ((const float4*)src)[2 * i + 1];
    a.x = to_tf32(a.x); a.y = to_tf32(a.y); a.z = to_tf32(a.z); a.w = to_tf32(a.w);
    b.x = to_tf32(b.x); b.y = to_tf32(b.y); b.z = to_tf32(b.z); b.w = to_tf32(b.w);
    perm_store8(dst + 8 * i, a, b);
}

// ---------------- rmsnorm (emits 16-wide k-permuted tf32 rows, A op) ------
__global__ void __launch_bounds__(256) rmsnorm_k(const float* __restrict__ x) {
    int row = blockIdx.x;
    const float4* xr = (const float4*)(x + (size_t)row * DIMD);
    int t = threadIdx.x;    // thread t owns k = 8t..8t+7

    float4 a = xr[2 * t];
    float4 b = xr[2 * t + 1];
    float ss = a.x*a.x + a.y*a.y + a.z*a.z + a.w*a.w
             + b.x*b.x + b.y*b.y + b.z*b.z + b.w*b.w;
    #pragma unroll
    for (int off = 16; off > 0; off >>= 1)
        ss += __shfl_xor_sync(0xffffffffu, ss, off);

    __shared__ float red[8];
    __shared__ float sscale;
    int warp = t >> 5, lane = t & 31;
    if (lane == 0) red[warp] = ss;
    __syncthreads();
    if (t == 0) {
        float tot = 0.f;
        #pragma unroll
        for (int i = 0; i < 8; i++) tot += red[i];
        sscale = rsqrtf(tot * (1.0f / DIMD) + 1.1920928955078125e-07f);
    }
    __syncthreads();
    float sc = sscale;

    float va[4] = {a.x, a.y, a.z, a.w};
    float vb[4] = {b.x, b.y, b.z, b.w};
    // half h=t&1: va[j]=k_{8h+j}, vb[j]=k_{8h+j+4} -> positions 4j+2h, 4j+2h+1
    float* og = g_xn + (size_t)row * DIMD + 16 * (t >> 1) + (t & 1) * 2;
    #pragma unroll
    for (int j = 0; j < 4; j++) {
        float2 p;
        p.x = to_tf32(va[j] * sc);
        p.y = to_tf32(vb[j] * sc);
        *(float2*)(og + 4 * j) = p;
    }
}

// ---------------- gate * causal dwconv * gate (16-perm o, A op) ----------
__global__ void __launch_bounds__(256) gateconv_k(const float* __restrict__ cw,
                                                  const float* __restrict__ cb,
                                                  const int* __restrict__ dil_p) {
    int dil = *dil_p;
    size_t idx = (size_t)blockIdx.x * blockDim.x + threadIdx.x;
    if (idx >= (size_t)MTOT * (DIMD / 4)) return;
    int r = (int)(idx % (DIMD / 4));
    int m = (int)(idx / (DIMD / 4));
    int s = m % SEQ;
    int gg = r >> 2, j = r & 3;
    int dbase = gg * 16 + j;

    const float* hr = g_h + (size_t)m * N1;
    const float* hp1 = hr - (size_t)dil * N1;
    const float* hp2 = hr - (size_t)(2 * dil) * N1;
    bool ok1 = (s >= dil), ok2 = (s >= 2 * dil);

    float o[4];
    #pragma unroll
    for (int i = 0; i < 4; i++) {
        int d = dbase + 4 * i;
        float w0 = cw[d * 3 + 0], w1 = cw[d * 3 + 1], w2 = cw[d * 3 + 2];
        float acc = cb[d] + w2 * (hr[d] * hr[2 * DIMD + d]);
        if (ok1) acc += w1 * (hp1[d] * hp1[2 * DIMD + d]);
        if (ok2) acc += w0 * (hp2[d] * hp2[2 * DIMD + d]);
        o[i] = to_tf32(hr[DIMD + d] * acc);
    }
    float4 st; st.x = o[0]; st.y = o[1]; st.z = o[2]; st.w = o[3];
    *(float4*)(g_o + (size_t)m * DIMD + gg * 16 + 4 * j) = st;
}

// ---------------- launch ----------------
extern "C" void kernel_launch(void* const* d_in, const int* in_sizes, int n_in,
                              void* d_out, int out_size) {
    const float* x   = (const float*)d_in[0];
    const float* We  = (const float*)d_in[1];
    const float* cw  = (const float*)d_in[2];
    const float* cb  = (const float*)d_in[3];
    const float* Wp  = (const float*)d_in[4];
    const float* cs  = (const float*)d_in[5];
    const int*   dil = (const int*)  d_in[6];
    float* out = (float*)d_out;

    float *p_xn, *p_h, *p_o, *p_We, *p_Wp;
    cudaGetSymbolAddress((void**)&p_xn, g_xn);
    cudaGetSymbolAddress((void**)&p_h,  g_h);
    cudaGetSymbolAddress((void**)&p_o,  g_o);
    cudaGetSymbolAddress((void**)&p_We, g_We);
    cudaGetSymbolAddress((void**)&p_Wp, g_Wp);

    cudaFuncSetAttribute(gemm_k<N1, false>, cudaFuncAttributeMaxDynamicSharedMemorySize, SMEM_SZ);
    cudaFuncSetAttribute(gemm_k<KD, true >, cudaFuncAttributeMaxDynamicSharedMemorySize, SMEM_SZ);

    {
        constexpr size_t TWE = (size_t)N1 * KD;
        constexpr size_t TWP = (size_t)KD * KD;
        round_perm_k<TWE><<<(unsigned)((TWE / 8 + 255) / 256), 256>>>(We, p_We);
        round_perm_k<TWP><<<(unsigned)((TWP / 8 + 255) / 256), 256>>>(Wp, p_Wp);
    }

    rmsnorm_k<<<MTOT, 256>>>(x);

    // h = xn @ We^T   [16384 x 6144]
    gemm_k<N1, false><<<dim3(N1 / BN, MTOT / BM), 256, SMEM_SZ>>>(p_xn, p_We, p_h, nullptr, nullptr);

    {
        size_t n = (size_t)MTOT * (DIMD / 4);
        gateconv_k<<<(unsigned)((n + 255) / 256), 256>>>(cw, cb, dil);
    }

    // out = x + cs * (o @ Wp^T)   [16384 x 2048]
    gemm_k<KD, true><<<dim3(KD / BN, MTOT / BM), 256, SMEM_SZ>>>(p_o, p_Wp, out, x, cs);
}

// round 12
// speedup vs baseline: 1.3988x; 1.0325x over previous
#include <cuda_runtime.h>
#include <cstdint>
#include <cstddef>

// ---------------- problem constants ----------------
#define DIMD   2048
#define MTOT   16384            // 4*4096 tokens
#define N1     6144             // 3*DIMD
#define KD     2048
#define SEQ    4096

// ---------------- scratch ----------------
// ALL GEMM operands (g_xn, g_o, g_We, g_Wp): 16-wide k-perm,
// pos 4j+i holds k=j+4i -> thread tig's float4 = {k=tig,tig+4,tig+8,tig+12}
// = fragments for TWO ks-steps in one LDS.128.
__device__ float g_xn[(size_t)MTOT * KD];
__device__ float g_h [(size_t)MTOT * N1];
__device__ float g_o [(size_t)MTOT * KD];
__device__ float g_We[(size_t)N1  * KD];
__device__ float g_Wp[(size_t)KD  * KD];

// ---------------- helpers ----------------
__device__ __forceinline__ float to_tf32(float x) {
    float r; asm("cvt.rna.tf32.f32 %0, %1;" : "=f"(r) : "f"(x)); return r;
}
__device__ __forceinline__ void cpasync16(void* smem, const void* gmem) {
    uint32_t s = (uint32_t)__cvta_generic_to_shared(smem);
    asm volatile("cp.async.cg.shared.global [%0], [%1], 16;" :: "r"(s), "l"(gmem));
}
#define CP_COMMIT() asm volatile("cp.async.commit_group;")
#define CP_WAIT1()  asm volatile("cp.async.wait_group 1;")

__device__ __forceinline__ uint4 lds128(uint32_t a) {
    uint4 v;
    asm volatile("ld.shared.v4.b32 {%0,%1,%2,%3}, [%4];"
                 : "=r"(v.x), "=r"(v.y), "=r"(v.z), "=r"(v.w) : "r"(a));
    return v;
}

__device__ __forceinline__ void mma_tf32(float c[4], uint32_t a0, uint32_t a1,
                                         uint32_t a2, uint32_t a3,
                                         uint32_t b0, uint32_t b1) {
    asm volatile(
        "mma.sync.aligned.m16n8k8.row.col.f32.tf32.tf32.f32 "
        "{%0,%1,%2,%3}, {%4,%5,%6,%7}, {%8,%9}, {%0,%1,%2,%3};"
        : "+f"(c[0]), "+f"(c[1]), "+f"(c[2]), "+f"(c[3])
        : "r"(a0), "r"(a1), "r"(a2), "r"(a3), "r"(b0), "r"(b1));
}

// ---------------- tf32 GEMM v12: C[M,N] = A[M,K] * B[N,K]^T ----------------
// CTA 128x256, 8 warps (2Mx4N), warp tile 64x64, BK=32, NSTG=3.
// Both operands 16-perm + key(row)=((row&1)<<2)|((row>>1)&3) swizzle ->
// conflict-free LDS.128 everywhere. Per kt: 32 LDS.128 feed 256 warp-MMAs.
// fb split in two ni-groups of 4 with group-level ping-pong (fb0/fb1, 16
// regs each); fa single-buffered per super-step, reloaded per-mi after use.
constexpr int BM = 128, BN = 256, BK = 32, NSTG = 3;
constexpr int ROW_F = 32;                            // floats per smem row
constexpr int A_FLOATS = BM * ROW_F;                 // 4096
constexpr int B_FLOATS = BN * ROW_F;                 // 8192
constexpr int STG_FLOATS = A_FLOATS + B_FLOATS;      // 12288
constexpr int STG_BYTES  = STG_FLOATS * 4;           // 49152
constexpr int SMEM_SZ = NSTG * STG_BYTES;            // 147456 B

template<int N, bool FUSE>
__global__ void __launch_bounds__(256, 1) gemm_k(const float* __restrict__ A,
                                                 const float* __restrict__ B,
                                                 float* __restrict__ C,
                                                 const float* __restrict__ xres,
                                                 const float* __restrict__ cs) {
    constexpr int K = KD;
    constexpr int KT = K / BK;    // 64
    extern __shared__ float smem[];
    const uint32_t sbase = (uint32_t)__cvta_generic_to_shared(smem);

    const int bm = blockIdx.y * BM;
    const int bn = blockIdx.x * BN;
    const int tid  = threadIdx.x;
    const int warp = tid >> 5, lane = tid & 31;
    const int wm = (warp & 1) * 64;
    const int wn = (warp >> 1) * 64;
    const int gid = lane >> 2, tig = lane & 3;

    float acc[4][8][4];
    #pragma unroll
    for (int mi = 0; mi < 4; mi++)
        #pragma unroll
        for (int ni = 0; ni < 8; ni++)
            #pragma unroll
            for (int r = 0; r < 4; r++) acc[mi][ni][r] = 0.f;

    const float* Abase = A + (size_t)bm * K;
    const float* Bbase = B + (size_t)bn * K;

    auto load_stage = [&](int kt) {
        float* sa = smem + (kt % NSTG) * STG_FLOATS;
        float* sb = sa + A_FLOATS;
        const float* Ag = Abase + kt * BK;
        const float* Bg = Bbase + kt * BK;
        #pragma unroll
        for (int i = 0; i < 4; i++) {
            int c = tid + i * 256;
            int row = c >> 3, ck = c & 7;
            int key = ((row & 1) << 2) | ((row >> 1) & 3);
            cpasync16(sa + row * ROW_F + ((ck ^ key) << 2),
                      Ag + (size_t)row * K + ck * 4);
        }
        #pragma unroll
        for (int i = 0; i < 8; i++) {
            int c = tid + i * 256;
            int row = c >> 3, ck = c & 7;
            int key = ((row & 1) << 2) | ((row >> 1) & 3);
            cpasync16(sb + row * ROW_F + ((ck ^ key) << 2),
                      Bg + (size_t)row * K + ck * 4);
        }
    };

    uint4 fa[4][2];   // [mi][row-half]; one super-step (2 ks)
    uint4 fb0[4];     // ni 0..3 of current super-step
    uint4 fb1[4];     // ni 4..7 of current super-step

    // per-thread invariants (bytes)
    const uint32_t key = (uint32_t)(((gid & 1) << 2) | ((gid >> 1) & 3));
    const uint32_t col0 = (uint32_t)((tig ^ key) << 4);         // super-step 0
    const uint32_t col1 = (uint32_t)(((4 | tig) ^ key) << 4);   // super-step 1
    const uint32_t arow = (uint32_t)(wm + gid) * 128;
    const uint32_t brow = (uint32_t)(A_FLOATS * 4) + (uint32_t)(wn + gid) * 128;

    auto ldfa = [&](int mi, uint32_t base) {
        fa[mi][0] = lds128(base + (uint32_t)(mi * 2048));
        fa[mi][1] = lds128(base + (uint32_t)(mi * 2048 + 1024));
    };
    // 8 MMAs: acc[mi][nib..nib+3], both halves of the super-step
    auto mma_g = [&](int mi, const uint4* fb, int nib) {
        #pragma unroll
        for (int j = 0; j < 4; j++) {
            int ni = nib + j;
            mma_tf32(acc[mi][ni], fa[mi][0].x, fa[mi][1].x,
                                 fa[mi][0].y, fa[mi][1].y, fb[j].x, fb[j].y);
            mma_tf32(acc[mi][ni], fa[mi][0].z, fa[mi][1].z,
                                 fa[mi][0].w, fa[mi][1].w, fb[j].z, fb[j].w);
        }
    };

    // prologue: 2 stages in flight, then fa(sp0) + fb0(ni0-3, sp0) of stage 0
    load_stage(0); CP_COMMIT();
    load_stage(1); CP_COMMIT();
    CP_WAIT1();
    __syncthreads();
    {
        const uint32_t aB = sbase + arow + col0;
        const uint32_t bB = sbase + brow + col0;
        #pragma unroll
        for (int mi = 0; mi < 4; mi++) ldfa(mi, aB);
        #pragma unroll
        for (int j = 0; j < 4; j++) fb0[j] = lds128(bB + (uint32_t)(j * 1024));
    }

    #pragma unroll 1
    for (int kt = 0; kt < KT; kt++) {
        const uint32_t stg = sbase + (uint32_t)(kt % NSTG) * STG_BYTES;
        const uint32_t aS = stg + arow;
        const uint32_t bS = stg + brow;

        // ---- super-step 0 ----
        // g0: mma(fb0, ni0-3) ; load fb1 <- sp0 ni4-7
        #pragma unroll
        for (int mi = 0; mi < 4; mi++) {
            fb1[mi] = lds128(bS + col0 + (uint32_t)((4 + mi) * 1024));
            mma_g(mi, fb0, 0);
        }
        if (kt + 2 < KT) load_stage(kt + 2);
        CP_COMMIT();
        // g1: mma(fb1, ni4-7) ; reload fa <- sp1 ; load fb0 <- sp1 ni0-3
        #pragma unroll
        for (int mi = 0; mi < 4; mi++) {
            mma_g(mi, fb1, 4);
            ldfa(mi, aS + col1);
            fb0[mi] = lds128(bS + col1 + (uint32_t)(mi * 1024));
        }

        // ---- super-step 1 ----
        // g0: mma(fb0, ni0-3) ; load fb1 <- sp1 ni4-7
        #pragma unroll
        for (int mi = 0; mi < 4; mi++) {
            fb1[mi] = lds128(bS + col1 + (uint32_t)((4 + mi) * 1024));
            mma_g(mi, fb0, 0);
        }
        // boundary, then g1: mma(fb1, ni4-7) ; load fa+fb0 <- next tile sp0
        if (kt + 1 < KT) {
            CP_WAIT1();
            __syncthreads();
            const uint32_t nstg = sbase + (uint32_t)((kt + 1) % NSTG) * STG_BYTES;
            const uint32_t naS = nstg + arow + col0;
            const uint32_t nbS = nstg + brow + col0;
            #pragma unroll
            for (int mi = 0; mi < 4; mi++) {
                mma_g(mi, fb1, 4);
                ldfa(mi, naS);
                fb0[mi] = lds128(nbS + (uint32_t)(mi * 1024));
            }
        } else {
            #pragma unroll
            for (int mi = 0; mi < 4; mi++) mma_g(mi, fb1, 4);
        }
    }

    // epilogue
    #pragma unroll
    for (int mi = 0; mi < 4; mi++) {
        #pragma unroll
        for (int ni = 0; ni < 8; ni++) {
            int r0 = bm + wm + mi * 16 + gid;
            int c0 = bn + wn + ni * 8 + tig * 2;
            #pragma unroll
            for (int h = 0; h < 2; h++) {
                int r = r0 + h * 8;
                size_t off = (size_t)r * N + c0;
                float v0 = acc[mi][ni][2 * h + 0];
                float v1 = acc[mi][ni][2 * h + 1];
                if (FUSE) {
                    v0 = xres[off]     + cs[c0]     * v0;
                    v1 = xres[off + 1] + cs[c0 + 1] * v1;
                }
                float2 st; st.x = v0; st.y = v1;
                *(float2*)(C + off) = st;
            }
        }
    }
}

// ---------------- prep: round weights to tf32 + 16-wide k-permute --------
template<size_t TOTAL>
__global__ void round_perm_k(const float* __restrict__ src, float* __restrict__ dst) {
    size_t i = (size_t)blockIdx.x * blockDim.x + threadIdx.x;   // 16-group idx
    if (i >= TOTAL / 16) return;
    const float4* s = (const float4*)src + 4 * i;
    float4 a = s[0], b = s[1], c = s[2], d = s[3];
    a.x = to_tf32(a.x); a.y = to_tf32(a.y); a.z = to_tf32(a.z); a.w = to_tf32(a.w);
    b.x = to_tf32(b.x); b.y = to_tf32(b.y); b.z = to_tf32(b.z); b.w = to_tf32(b.w);
    c.x = to_tf32(c.x); c.y = to_tf32(c.y); c.z = to_tf32(c.z); c.w = to_tf32(c.w);
    d.x = to_tf32(d.x); d.y = to_tf32(d.y); d.z = to_tf32(d.z); d.w = to_tf32(d.w);
    float4* o = (float4*)dst + 4 * i;
    o[0] = make_float4(a.x, b.x, c.x, d.x);
    o[1] = make_float4(a.y, b.y, c.y, d.y);
    o[2] = make_float4(a.z, b.z, c.z, d.z);
    o[3] = make_float4(a.w, b.w, c.w, d.w);
}

// ---------------- rmsnorm (emits 16-wide k-permuted tf32 rows) -----------
__global__ void __launch_bounds__(256) rmsnorm_k(const float* __restrict__ x) {
    int row = blockIdx.x;
    const float4* xr = (const float4*)(x + (size_t)row * DIMD);
    int t = threadIdx.x;    // thread t owns k = 8t..8t+7

    float4 a = xr[2 * t];
    float4 b = xr[2 * t + 1];
    float ss = a.x*a.x + a.y*a.y + a.z*a.z + a.w*a.w
             + b.x*b.x + b.y*b.y + b.z*b.z + b.w*b.w;
    #pragma unroll
    for (int off = 16; off > 0; off >>= 1)
        ss += __shfl_xor_sync(0xffffffffu, ss, off);

    __shared__ float red[8];
    __shared__ float sscale;
    int warp = t >> 5, lane = t & 31;
    if (lane == 0) red[warp] = ss;
    __syncthreads();
    if (t == 0) {
        float tot = 0.f;
        #pragma unroll
        for (int i = 0; i < 8; i++) tot += red[i];
        sscale = rsqrtf(tot * (1.0f / DIMD) + 1.1920928955078125e-07f);
    }
    __syncthreads();
    float sc = sscale;

    float va[4] = {a.x, a.y, a.z, a.w};
    float vb[4] = {b.x, b.y, b.z, b.w};
    // half h=t&1: va[j]=k_{8h+j}, vb[j]=k_{8h+j+4} -> positions 4j+2h, 4j+2h+1
    float* og = g_xn + (size_t)row * DIMD + 16 * (t >> 1) + (t & 1) * 2;
    #pragma unroll
    for (int j = 0; j < 4; j++) {
        float2 p;
        p.x = to_tf32(va[j] * sc);
        p.y = to_tf32(vb[j] * sc);
        *(float2*)(og + 4 * j) = p;
    }
}

// ---------------- gate * causal dwconv * gate (16-perm o) ----------------
__global__ void __launch_bounds__(256) gateconv_k(const float* __restrict__ cw,
                                                  const float* __restrict__ cb,
                                                  const int* __restrict__ dil_p) {
    int dil = *dil_p;
    size_t idx = (size_t)blockIdx.x * blockDim.x + threadIdx.x;
    if (idx >= (size_t)MTOT * (DIMD / 4)) return;
    int r = (int)(idx % (DIMD / 4));
    int m = (int)(idx / (DIMD / 4));
    int s = m % SEQ;
    int gg = r >> 2, j = r & 3;
    int dbase = gg * 16 + j;

    const float* hr = g_h + (size_t)m * N1;
    const float* hp1 = hr - (size_t)dil * N1;
    const float* hp2 = hr - (size_t)(2 * dil) * N1;
    bool ok1 = (s >= dil), ok2 = (s >= 2 * dil);

    float o[4];
    #pragma unroll
    for (int i = 0; i < 4; i++) {
        int d = dbase + 4 * i;
        float w0 = cw[d * 3 + 0], w1 = cw[d * 3 + 1], w2 = cw[d * 3 + 2];
        float acc = cb[d] + w2 * (hr[d] * hr[2 * DIMD + d]);
        if (ok1) acc += w1 * (hp1[d] * hp1[2 * DIMD + d]);
        if (ok2) acc += w0 * (hp2[d] * hp2[2 * DIMD + d]);
        o[i] = to_tf32(hr[DIMD + d] * acc);
    }
    float4 st; st.x = o[0]; st.y = o[1]; st.z = o[2]; st.w = o[3];
    *(float4*)(g_o + (size_t)m * DIMD + gg * 16 + 4 * j) = st;
}

// ---------------- launch ----------------
extern "C" void kernel_launch(void* const* d_in, const int* in_sizes, int n_in,
                              void* d_out, int out_size) {
    const float* x   = (const float*)d_in[0];
    const float* We  = (const float*)d_in[1];
    const float* cw  = (const float*)d_in[2];
    const float* cb  = (const float*)d_in[3];
    const float* Wp  = (const float*)d_in[4];
    const float* cs  = (const float*)d_in[5];
    const int*   dil = (const int*)  d_in[6];
    float* out = (float*)d_out;

    float *p_xn, *p_h, *p_o, *p_We, *p_Wp;
    cudaGetSymbolAddress((void**)&p_xn, g_xn);
    cudaGetSymbolAddress((void**)&p_h,  g_h);
    cudaGetSymbolAddress((void**)&p_o,  g_o);
    cudaGetSymbolAddress((void**)&p_We, g_We);
    cudaGetSymbolAddress((void**)&p_Wp, g_Wp);

    cudaFuncSetAttribute(gemm_k<N1, false>, cudaFuncAttributeMaxDynamicSharedMemorySize, SMEM_SZ);
    cudaFuncSetAttribute(gemm_k<KD, true >, cudaFuncAttributeMaxDynamicSharedMemorySize, SMEM_SZ);

    {
        constexpr size_t TWE = (size_t)N1 * KD;
        constexpr size_t TWP = (size_t)KD * KD;
        round_perm_k<TWE><<<(unsigned)((TWE / 16 + 255) / 256), 256>>>(We, p_We);
        round_perm_k<TWP><<<(unsigned)((TWP / 16 + 255) / 256), 256>>>(Wp, p_Wp);
    }

    rmsnorm_k<<<MTOT, 256>>>(x);

    // h = xn @ We^T   [16384 x 6144]
    gemm_k<N1, false><<<dim3(N1 / BN, MTOT / BM), 256, SMEM_SZ>>>(p_xn, p_We, p_h, nullptr, nullptr);

    {
        size_t n = (size_t)MTOT * (DIMD / 4);
        gateconv_k<<<(unsigned)((n + 255) / 256), 256>>>(cw, cb, dil);
    }

    // out = x + cs * (o @ Wp^T)   [16384 x 2048]
    gemm_k<KD, true><<<dim3(KD / BN, MTOT / BM), 256, SMEM_SZ>>>(p_o, p_Wp, out, x, cs);
}

// round 13
// speedup vs baseline: 1.4208x; 1.0157x over previous
#include <cuda_runtime.h>
#include <cstdint>
#include <cstddef>

// ---------------- problem constants ----------------
#define DIMD   2048
#define MTOT   16384            // 4*4096 tokens
#define N1     6144             // 3*DIMD
#define KD     2048
#define SEQ    4096

// ---------------- scratch ----------------
// ALL GEMM operands (g_xn, g_o, g_We, g_Wp): 16-wide k-perm,
// pos 4j+i holds k=j+4i -> thread tig's float4 = {k=tig,tig+4,tig+8,tig+12}
// = fragments for TWO ks-steps in one LDS.128.
__device__ float g_xn[(size_t)MTOT * KD];
__device__ float g_h [(size_t)MTOT * N1];
__device__ float g_o [(size_t)MTOT * KD];
__device__ float g_We[(size_t)N1  * KD];
__device__ float g_Wp[(size_t)KD  * KD];

// ---------------- helpers ----------------
__device__ __forceinline__ float to_tf32(float x) {
    float r; asm("cvt.rna.tf32.f32 %0, %1;" : "=f"(r) : "f"(x)); return r;
}
__device__ __forceinline__ void cpasync16(void* smem, const void* gmem) {
    uint32_t s = (uint32_t)__cvta_generic_to_shared(smem);
    asm volatile("cp.async.cg.shared.global [%0], [%1], 16;" :: "r"(s), "l"(gmem));
}
#define CP_COMMIT() asm volatile("cp.async.commit_group;")
#define CP_WAIT2()  asm volatile("cp.async.wait_group 2;")

__device__ __forceinline__ uint4 lds128(uint32_t a) {
    uint4 v;
    asm volatile("ld.shared.v4.b32 {%0,%1,%2,%3}, [%4];"
                 : "=r"(v.x), "=r"(v.y), "=r"(v.z), "=r"(v.w) : "r"(a));
    return v;
}

__device__ __forceinline__ void mma_tf32(float c[4], uint32_t a0, uint32_t a1,
                                         uint32_t a2, uint32_t a3,
                                         uint32_t b0, uint32_t b1) {
    asm volatile(
        "mma.sync.aligned.m16n8k8.row.col.f32.tf32.tf32.f32 "
        "{%0,%1,%2,%3}, {%4,%5,%6,%7}, {%8,%9}, {%0,%1,%2,%3};"
        : "+f"(c[0]), "+f"(c[1]), "+f"(c[2]), "+f"(c[3])
        : "r"(a0), "r"(a1), "r"(a2), "r"(a3), "r"(b0), "r"(b1));
}

// ---------------- tf32 GEMM v13: C[M,N] = A[M,K] * B[N,K]^T ----------------
// CTA 128x256, 8 warps (2Mx4N), warp tile 64x64, BK=32, NSTG=4.
// Both operands 16-perm + key(row)=((row&1)<<2)|((row>>1)&3) swizzle ->
// conflict-free LDS.128 everywhere (32 LDS.128 feed 256 warp-MMAs per kt).
// Prefetch distance 3 + wait_group 2: the boundary wait is pre-satisfied,
// exposing only the barrier. fb group-level ping-pong, fa per-mi reload.
constexpr int BM = 128, BN = 256, BK = 32, NSTG = 4;
constexpr int ROW_F = 32;                            // floats per smem row
constexpr int A_FLOATS = BM * ROW_F;                 // 4096
constexpr int B_FLOATS = BN * ROW_F;                 // 8192
constexpr int STG_FLOATS = A_FLOATS + B_FLOATS;      // 12288
constexpr int STG_BYTES  = STG_FLOATS * 4;           // 49152
constexpr int SMEM_SZ = NSTG * STG_BYTES;            // 196608 B

template<int N, bool FUSE>
__global__ void __launch_bounds__(256, 1) gemm_k(const float* __restrict__ A,
                                                 const float* __restrict__ B,
                                                 float* __restrict__ C,
                                                 const float* __restrict__ xres,
                                                 const float* __restrict__ cs) {
    constexpr int K = KD;
    constexpr int KT = K / BK;    // 64
    extern __shared__ float smem[];
    const uint32_t sbase = (uint32_t)__cvta_generic_to_shared(smem);

    const int bm = blockIdx.y * BM;
    const int bn = blockIdx.x * BN;
    const int tid  = threadIdx.x;
    const int warp = tid >> 5, lane = tid & 31;
    const int wm = (warp & 1) * 64;
    const int wn = (warp >> 1) * 64;
    const int gid = lane >> 2, tig = lane & 3;

    float acc[4][8][4];
    #pragma unroll
    for (int mi = 0; mi < 4; mi++)
        #pragma unroll
        for (int ni = 0; ni < 8; ni++)
            #pragma unroll
            for (int r = 0; r < 4; r++) acc[mi][ni][r] = 0.f;

    const float* Abase = A + (size_t)bm * K;
    const float* Bbase = B + (size_t)bn * K;

    auto load_stage = [&](int kt) {
        float* sa = smem + (kt % NSTG) * STG_FLOATS;
        float* sb = sa + A_FLOATS;
        const float* Ag = Abase + kt * BK;
        const float* Bg = Bbase + kt * BK;
        #pragma unroll
        for (int i = 0; i < 4; i++) {
            int c = tid + i * 256;
            int row = c >> 3, ck = c & 7;
            int key = ((row & 1) << 2) | ((row >> 1) & 3);
            cpasync16(sa + row * ROW_F + ((ck ^ key) << 2),
                      Ag + (size_t)row * K + ck * 4);
        }
        #pragma unroll
        for (int i = 0; i < 8; i++) {
            int c = tid + i * 256;
            int row = c >> 3, ck = c & 7;
            int key = ((row & 1) << 2) | ((row >> 1) & 3);
            cpasync16(sb + row * ROW_F + ((ck ^ key) << 2),
                      Bg + (size_t)row * K + ck * 4);
        }
    };

    uint4 fa[4][2];   // [mi][row-half]; one super-step (2 ks)
    uint4 fb0[4];     // ni 0..3 of current super-step
    uint4 fb1[4];     // ni 4..7 of current super-step

    // per-thread invariants (bytes)
    const uint32_t key = (uint32_t)(((gid & 1) << 2) | ((gid >> 1) & 3));
    const uint32_t col0 = (uint32_t)((tig ^ key) << 4);         // super-step 0
    const uint32_t col1 = (uint32_t)(((4 | tig) ^ key) << 4);   // super-step 1
    const uint32_t arow = (uint32_t)(wm + gid) * 128;
    const uint32_t brow = (uint32_t)(A_FLOATS * 4) + (uint32_t)(wn + gid) * 128;

    auto ldfa = [&](int mi, uint32_t base) {
        fa[mi][0] = lds128(base + (uint32_t)(mi * 2048));
        fa[mi][1] = lds128(base + (uint32_t)(mi * 2048 + 1024));
    };
    // 8 MMAs: acc[mi][nib..nib+3], both halves of the super-step
    auto mma_g = [&](int mi, const uint4* fb, int nib) {
        #pragma unroll
        for (int j = 0; j < 4; j++) {
            int ni = nib + j;
            mma_tf32(acc[mi][ni], fa[mi][0].x, fa[mi][1].x,
                                 fa[mi][0].y, fa[mi][1].y, fb[j].x, fb[j].y);
            mma_tf32(acc[mi][ni], fa[mi][0].z, fa[mi][1].z,
                                 fa[mi][0].w, fa[mi][1].w, fb[j].z, fb[j].w);
        }
    };

    // prologue: 3 stages in flight, then fa(sp0) + fb0(ni0-3, sp0) of stage 0
    load_stage(0); CP_COMMIT();
    load_stage(1); CP_COMMIT();
    load_stage(2); CP_COMMIT();
    CP_WAIT2();                  // stage 0 ready
    __syncthreads();
    {
        const uint32_t aB = sbase + arow + col0;
        const uint32_t bB = sbase + brow + col0;
        #pragma unroll
        for (int mi = 0; mi < 4; mi++) ldfa(mi, aB);
        #pragma unroll
        for (int j = 0; j < 4; j++) fb0[j] = lds128(bB + (uint32_t)(j * 1024));
    }

    #pragma unroll 1
    for (int kt = 0; kt < KT; kt++) {
        const uint32_t stg = sbase + (uint32_t)(kt % NSTG) * STG_BYTES;
        const uint32_t aS = stg + arow;
        const uint32_t bS = stg + brow;

        // ---- super-step 0 ----
        // g0: mma(fb0, ni0-3) ; load fb1 <- sp0 ni4-7
        #pragma unroll
        for (int mi = 0; mi < 4; mi++) {
            fb1[mi] = lds128(bS + col0 + (uint32_t)((4 + mi) * 1024));
            mma_g(mi, fb0, 0);
        }
        if (kt + 3 < KT) load_stage(kt + 3);   // overwrites (kt-1)%4: safe,
        CP_COMMIT();                           // reads done before last barrier
        // g1: mma(fb1, ni4-7) ; reload fa <- sp1 ; load fb0 <- sp1 ni0-3
        #pragma unroll
        for (int mi = 0; mi < 4; mi++) {
            mma_g(mi, fb1, 4);
            ldfa(mi, aS + col1);
            fb0[mi] = lds128(bS + col1 + (uint32_t)(mi * 1024));
        }

        // ---- super-step 1 ----
        // g0: mma(fb0, ni0-3) ; load fb1 <- sp1 ni4-7
        #pragma unroll
        for (int mi = 0; mi < 4; mi++) {
            fb1[mi] = lds128(bS + col1 + (uint32_t)((4 + mi) * 1024));
            mma_g(mi, fb0, 0);
        }
        // boundary, then g1: mma(fb1, ni4-7) ; load fa+fb0 <- next tile sp0
        if (kt + 1 < KT) {
            CP_WAIT2();                        // stage kt+1 complete (in-order)
            __syncthreads();
            const uint32_t nstg = sbase + (uint32_t)((kt + 1) % NSTG) * STG_BYTES;
            const uint32_t naS = nstg + arow + col0;
            const uint32_t nbS = nstg + brow + col0;
            #pragma unroll
            for (int mi = 0; mi < 4; mi++) {
                mma_g(mi, fb1, 4);
                ldfa(mi, naS);
                fb0[mi] = lds128(nbS + (uint32_t)(mi * 1024));
            }
        } else {
            #pragma unroll
            for (int mi = 0; mi < 4; mi++) mma_g(mi, fb1, 4);
        }
    }

    // epilogue
    #pragma unroll
    for (int mi = 0; mi < 4; mi++) {
        #pragma unroll
        for (int ni = 0; ni < 8; ni++) {
            int r0 = bm + wm + mi * 16 + gid;
            int c0 = bn + wn + ni * 8 + tig * 2;
            #pragma unroll
            for (int h = 0; h < 2; h++) {
                int r = r0 + h * 8;
                size_t off = (size_t)r * N + c0;
                float v0 = acc[mi][ni][2 * h + 0];
                float v1 = acc[mi][ni][2 * h + 1];
                if (FUSE) {
                    v0 = xres[off]     + cs[c0]     * v0;
                    v1 = xres[off + 1] + cs[c0 + 1] * v1;
                }
                float2 st; st.x = v0; st.y = v1;
                *(float2*)(C + off) = st;
            }
        }
    }
}

// ---------------- prep: round weights to tf32 + 16-wide k-permute --------
template<size_t TOTAL>
__global__ void round_perm_k(const float* __restrict__ src, float* __restrict__ dst) {
    size_t i = (size_t)blockIdx.x * blockDim.x + threadIdx.x;   // 16-group idx
    if (i >= TOTAL / 16) return;
    const float4* s = (const float4*)src + 4 * i;
    float4 a = s[0], b = s[1], c = s[2], d = s[3];
    a.x = to_tf32(a.x); a.y = to_tf32(a.y); a.z = to_tf32(a.z); a.w = to_tf32(a.w);
    b.x = to_tf32(b.x); b.y = to_tf32(b.y); b.z = to_tf32(b.z); b.w = to_tf32(b.w);
    c.x = to_tf32(c.x); c.y = to_tf32(c.y); c.z = to_tf32(c.z); c.w = to_tf32(c.w);
    d.x = to_tf32(d.x); d.y = to_tf32(d.y); d.z = to_tf32(d.z); d.w = to_tf32(d.w);
    float4* o = (float4*)dst + 4 * i;
    o[0] = make_float4(a.x, b.x, c.x, d.x);
    o[1] = make_float4(a.y, b.y, c.y, d.y);
    o[2] = make_float4(a.z, b.z, c.z, d.z);
    o[3] = make_float4(a.w, b.w, c.w, d.w);
}

// ---------------- rmsnorm (emits 16-wide k-permuted tf32 rows) -----------
__global__ void __launch_bounds__(256) rmsnorm_k(const float* __restrict__ x) {
    int row = blockIdx.x;
    const float4* xr = (const float4*)(x + (size_t)row * DIMD);
    int t = threadIdx.x;    // thread t owns k = 8t..8t+7

    float4 a = xr[2 * t];
    float4 b = xr[2 * t + 1];
    float ss = a.x*a.x + a.y*a.y + a.z*a.z + a.w*a.w
             + b.x*b.x + b.y*b.y + b.z*b.z + b.w*b.w;
    #pragma unroll
    for (int off = 16; off > 0; off >>= 1)
        ss += __shfl_xor_sync(0xffffffffu, ss, off);

    __shared__ float red[8];
    __shared__ float sscale;
    int warp = t >> 5, lane = t & 31;
    if (lane == 0) red[warp] = ss;
    __syncthreads();
    if (t == 0) {
        float tot = 0.f;
        #pragma unroll
        for (int i = 0; i < 8; i++) tot += red[i];
        sscale = rsqrtf(tot * (1.0f / DIMD) + 1.1920928955078125e-07f);
    }
    __syncthreads();
    float sc = sscale;

    float va[4] = {a.x, a.y, a.z, a.w};
    float vb[4] = {b.x, b.y, b.z, b.w};
    // half h=t&1: va[j]=k_{8h+j}, vb[j]=k_{8h+j+4} -> positions 4j+2h, 4j+2h+1
    float* og = g_xn + (size_t)row * DIMD + 16 * (t >> 1) + (t & 1) * 2;
    #pragma unroll
    for (int j = 0; j < 4; j++) {
        float2 p;
        p.x = to_tf32(va[j] * sc);
        p.y = to_tf32(vb[j] * sc);
        *(float2*)(og + 4 * j) = p;
    }
}

// ---------------- gate * causal dwconv * gate (16-perm o) ----------------
__global__ void __launch_bounds__(256) gateconv_k(const float* __restrict__ cw,
                                                  const float* __restrict__ cb,
                                                  const int* __restrict__ dil_p) {
    int dil = *dil_p;
    size_t idx = (size_t)blockIdx.x * blockDim.x + threadIdx.x;
    if (idx >= (size_t)MTOT * (DIMD / 4)) return;
    int r = (int)(idx % (DIMD / 4));
    int m = (int)(idx / (DIMD / 4));
    int s = m % SEQ;
    int gg = r >> 2, j = r & 3;
    int dbase = gg * 16 + j;

    const float* hr = g_h + (size_t)m * N1;
    const float* hp1 = hr - (size_t)dil * N1;
    const float* hp2 = hr - (size_t)(2 * dil) * N1;
    bool ok1 = (s >= dil), ok2 = (s >= 2 * dil);

    float o[4];
    #pragma unroll
    for (int i = 0; i < 4; i++) {
        int d = dbase + 4 * i;
        float w0 = cw[d * 3 + 0], w1 = cw[d * 3 + 1], w2 = cw[d * 3 + 2];
        float acc = cb[d] + w2 * (hr[d] * hr[2 * DIMD + d]);
        if (ok1) acc += w1 * (hp1[d] * hp1[2 * DIMD + d]);
        if (ok2) acc += w0 * (hp2[d] * hp2[2 * DIMD + d]);
        o[i] = to_tf32(hr[DIMD + d] * acc);
    }
    float4 st; st.x = o[0]; st.y = o[1]; st.z = o[2]; st.w = o[3];
    *(float4*)(g_o + (size_t)m * DIMD + gg * 16 + 4 * j) = st;
}

// ---------------- launch ----------------
extern "C" void kernel_launch(void* const* d_in, const int* in_sizes, int n_in,
                              void* d_out, int out_size) {
    const float* x   = (const float*)d_in[0];
    const float* We  = (const float*)d_in[1];
    const float* cw  = (const float*)d_in[2];
    const float* cb  = (const float*)d_in[3];
    const float* Wp  = (const float*)d_in[4];
    const float* cs  = (const float*)d_in[5];
    const int*   dil = (const int*)  d_in[6];
    float* out = (float*)d_out;

    float *p_xn, *p_h, *p_o, *p_We, *p_Wp;
    cudaGetSymbolAddress((void**)&p_xn, g_xn);
    cudaGetSymbolAddress((void**)&p_h,  g_h);
    cudaGetSymbolAddress((void**)&p_o,  g_o);
    cudaGetSymbolAddress((void**)&p_We, g_We);
    cudaGetSymbolAddress((void**)&p_Wp, g_Wp);

    cudaFuncSetAttribute(gemm_k<N1, false>, cudaFuncAttributeMaxDynamicSharedMemorySize, SMEM_SZ);
    cudaFuncSetAttribute(gemm_k<KD, true >, cudaFuncAttributeMaxDynamicSharedMemorySize, SMEM_SZ);

    {
        constexpr size_t TWE = (size_t)N1 * KD;
        constexpr size_t TWP = (size_t)KD * KD;
        round_perm_k<TWE><<<(unsigned)((TWE / 16 + 255) / 256), 256>>>(We, p_We);
        round_perm_k<TWP><<<(unsigned)((TWP / 16 + 255) / 256), 256>>>(Wp, p_Wp);
    }

    rmsnorm_k<<<MTOT, 256>>>(x);

    // h = xn @ We^T   [16384 x 6144]
    gemm_k<N1, false><<<dim3(N1 / BN, MTOT / BM), 256, SMEM_SZ>>>(p_xn, p_We, p_h, nullptr, nullptr);

    {
        size_t n = (size_t)MTOT * (DIMD / 4);
        gateconv_k<<<(unsigned)((n + 255) / 256), 256>>>(cw, cb, dil);
    }

    // out = x + cs * (o @ Wp^T)   [16384 x 2048]
    gemm_k<KD, true><<<dim3(KD / BN, MTOT / BM), 256, SMEM_SZ>>>(p_o, p_Wp, out, x, cs);
}

// round 14
// speedup vs baseline: 2.3945x; 1.6853x over previous
#include <cuda_runtime.h>
#include <cuda_fp16.h>
#include <cstdint>
#include <cstddef>

// ---------------- problem constants ----------------
#define DIMD   2048
#define MTOT   16384            // 4*4096 tokens
#define N1     6144             // 3*DIMD
#define KD     2048
#define SEQ    4096

// ---------------- scratch ----------------
// GEMM operands in fp16 with 64-wide k-permutation:
// within each 64-k group, 16B chunk c = 4*sp + t (sp in 0..1, t in 0..3)
// holds k = 32sp + 2t + {0,1,8,9,16,17,24,25}  -> one LDS.128 per thread
// = A/B fragments for TWO m16n8k16 steps.
__device__ __half g_xn[(size_t)MTOT * KD];
__device__ float  g_h [(size_t)MTOT * N1];
__device__ __half g_o [(size_t)MTOT * KD];
__device__ __half g_We[(size_t)N1  * KD];
__device__ __half g_Wp[(size_t)KD  * KD];

// ---------------- helpers ----------------
__device__ __forceinline__ uint32_t pk(float a, float b) {
    __half2 h = __floats2half2_rn(a, b);
    return *reinterpret_cast<uint32_t*>(&h);
}
__device__ __forceinline__ void cpasync16(void* smem, const void* gmem) {
    uint32_t s = (uint32_t)__cvta_generic_to_shared(smem);
    asm volatile("cp.async.cg.shared.global [%0], [%1], 16;" :: "r"(s), "l"(gmem));
}
#define CP_COMMIT() asm volatile("cp.async.commit_group;")
#define CP_WAIT2()  asm volatile("cp.async.wait_group 2;")

__device__ __forceinline__ uint4 lds128(uint32_t a) {
    uint4 v;
    asm volatile("ld.shared.v4.b32 {%0,%1,%2,%3}, [%4];"
                 : "=r"(v.x), "=r"(v.y), "=r"(v.z), "=r"(v.w) : "r"(a));
    return v;
}

__device__ __forceinline__ void mma_f16(float c[4], uint32_t a0, uint32_t a1,
                                        uint32_t a2, uint32_t a3,
                                        uint32_t b0, uint32_t b1) {
    asm volatile(
        "mma.sync.aligned.m16n8k16.row.col.f32.f16.f16.f32 "
        "{%0,%1,%2,%3}, {%4,%5,%6,%7}, {%8,%9}, {%0,%1,%2,%3};"
        : "+f"(c[0]), "+f"(c[1]), "+f"(c[2]), "+f"(c[3])
        : "r"(a0), "r"(a1), "r"(a2), "r"(a3), "r"(b0), "r"(b1));
}

// ---------------- fp16 GEMM v14: C[M,N] = A[M,K] * B[N,K]^T ---------------
// CTA 128x256, 8 warps (2Mx4N), warp tile 64x64, BK=64 (fp16, 128B rows),
// NSTG=4, prefetch distance 3. Same conflict-free XOR swizzle
// key(row)=((row&1)<<2)|((row>>1)&3) and fb ping-pong / fa reload schedule
// as v13; each mma is m16n8k16 so K advance per kt doubles (KT=32).
constexpr int BM = 128, BN = 256, NSTG = 4;
constexpr int BKH = 64;                              // halves per k-tile
constexpr int ROW_H = 64;                            // halves per smem row (128B)
constexpr int A_HALVES = BM * ROW_H;                 // 8192
constexpr int B_HALVES = BN * ROW_H;                 // 16384
constexpr int STG_HALVES = A_HALVES + B_HALVES;      // 24576
constexpr int STG_BYTES  = STG_HALVES * 2;           // 49152
constexpr int SMEM_SZ = NSTG * STG_BYTES;            // 196608 B

template<int N, bool FUSE>
__global__ void __launch_bounds__(256, 1) gemm_k(const __half* __restrict__ A,
                                                 const __half* __restrict__ B,
                                                 float* __restrict__ C,
                                                 const float* __restrict__ xres,
                                                 const float* __restrict__ cs) {
    constexpr int K = KD;
    constexpr int KT = K / BKH;   // 32
    extern __shared__ __half smem[];
    const uint32_t sbase = (uint32_t)__cvta_generic_to_shared(smem);

    const int bm = blockIdx.y * BM;
    const int bn = blockIdx.x * BN;
    const int tid  = threadIdx.x;
    const int warp = tid >> 5, lane = tid & 31;
    const int wm = (warp & 1) * 64;
    const int wn = (warp >> 1) * 64;
    const int gid = lane >> 2, tig = lane & 3;

    float acc[4][8][4];
    #pragma unroll
    for (int mi = 0; mi < 4; mi++)
        #pragma unroll
        for (int ni = 0; ni < 8; ni++)
            #pragma unroll
            for (int r = 0; r < 4; r++) acc[mi][ni][r] = 0.f;

    const __half* Abase = A + (size_t)bm * K;
    const __half* Bbase = B + (size_t)bn * K;

    auto load_stage = [&](int kt) {
        __half* sa = smem + (kt % NSTG) * STG_HALVES;
        __half* sb = sa + A_HALVES;
        const __half* Ag = Abase + kt * BKH;
        const __half* Bg = Bbase + kt * BKH;
        #pragma unroll
        for (int i = 0; i < 4; i++) {           // A: 1024 chunks, 4/thread
            int c = tid + i * 256;
            int row = c >> 3, ck = c & 7;
            int key = ((row & 1) << 2) | ((row >> 1) & 3);
            cpasync16(sa + row * ROW_H + ((ck ^ key) << 3),
                      Ag + (size_t)row * K + ck * 8);
        }
        #pragma unroll
        for (int i = 0; i < 8; i++) {           // B: 2048 chunks, 8/thread
            int c = tid + i * 256;
            int row = c >> 3, ck = c & 7;
            int key = ((row & 1) << 2) | ((row >> 1) & 3);
            cpasync16(sb + row * ROW_H + ((ck ^ key) << 3),
                      Bg + (size_t)row * K + ck * 8);
        }
    };

    uint4 fa[4][2];   // [mi][row-half]; one super-step (2 k16-steps)
    uint4 fb0[4];     // ni 0..3
    uint4 fb1[4];     // ni 4..7

    // per-thread invariants (bytes)
    const uint32_t key = (uint32_t)(((gid & 1) << 2) | ((gid >> 1) & 3));
    const uint32_t col0 = (uint32_t)((tig ^ key) << 4);         // sp0
    const uint32_t col1 = (uint32_t)(((4 | tig) ^ key) << 4);   // sp1
    const uint32_t arow = (uint32_t)(wm + gid) * 128;
    const uint32_t brow = (uint32_t)(A_HALVES * 2) + (uint32_t)(wn + gid) * 128;

    auto ldfa = [&](int mi, uint32_t base) {
        fa[mi][0] = lds128(base + (uint32_t)(mi * 2048));
        fa[mi][1] = lds128(base + (uint32_t)(mi * 2048 + 1024));
    };
    // 8 k16-MMAs: acc[mi][nib..nib+3], both k16-steps of the super-step
    auto mma_g = [&](int mi, const uint4* fb, int nib) {
        #pragma unroll
        for (int j = 0; j < 4; j++) {
            int ni = nib + j;
            mma_f16(acc[mi][ni], fa[mi][0].x, fa[mi][1].x,
                                fa[mi][0].y, fa[mi][1].y, fb[j].x, fb[j].y);
            mma_f16(acc[mi][ni], fa[mi][0].z, fa[mi][1].z,
                                fa[mi][0].w, fa[mi][1].w, fb[j].z, fb[j].w);
        }
    };

    // prologue: 3 stages in flight, then fa(sp0) + fb0(ni0-3, sp0) of stage 0
    load_stage(0); CP_COMMIT();
    load_stage(1); CP_COMMIT();
    load_stage(2); CP_COMMIT();
    CP_WAIT2();
    __syncthreads();
    {
        const uint32_t aB = sbase + arow + col0;
        const uint32_t bB = sbase + brow + col0;
        #pragma unroll
        for (int mi = 0; mi < 4; mi++) ldfa(mi, aB);
        #pragma unroll
        for (int j = 0; j < 4; j++) fb0[j] = lds128(bB + (uint32_t)(j * 1024));
    }

    #pragma unroll 1
    for (int kt = 0; kt < KT; kt++) {
        const uint32_t stg = sbase + (uint32_t)(kt % NSTG) * STG_BYTES;
        const uint32_t aS = stg + arow;
        const uint32_t bS = stg + brow;

        // ---- super-step 0 ----
        #pragma unroll
        for (int mi = 0; mi < 4; mi++) {
            fb1[mi] = lds128(bS + col0 + (uint32_t)((4 + mi) * 1024));
            mma_g(mi, fb0, 0);
        }
        if (kt + 3 < KT) load_stage(kt + 3);
        CP_COMMIT();
        #pragma unroll
        for (int mi = 0; mi < 4; mi++) {
            mma_g(mi, fb1, 4);
            ldfa(mi, aS + col1);
            fb0[mi] = lds128(bS + col1 + (uint32_t)(mi * 1024));
        }

        // ---- super-step 1 ----
        #pragma unroll
        for (int mi = 0; mi < 4; mi++) {
            fb1[mi] = lds128(bS + col1 + (uint32_t)((4 + mi) * 1024));
            mma_g(mi, fb0, 0);
        }
        if (kt + 1 < KT) {
            CP_WAIT2();
            __syncthreads();
            const uint32_t nstg = sbase + (uint32_t)((kt + 1) % NSTG) * STG_BYTES;
            const uint32_t naS = nstg + arow + col0;
            const uint32_t nbS = nstg + brow + col0;
            #pragma unroll
            for (int mi = 0; mi < 4; mi++) {
                mma_g(mi, fb1, 4);
                ldfa(mi, naS);
                fb0[mi] = lds128(nbS + (uint32_t)(mi * 1024));
            }
        } else {
            #pragma unroll
            for (int mi = 0; mi < 4; mi++) mma_g(mi, fb1, 4);
        }
    }

    // epilogue
    #pragma unroll
    for (int mi = 0; mi < 4; mi++) {
        #pragma unroll
        for (int ni = 0; ni < 8; ni++) {
            int r0 = bm + wm + mi * 16 + gid;
            int c0 = bn + wn + ni * 8 + tig * 2;
            #pragma unroll
            for (int h = 0; h < 2; h++) {
                int r = r0 + h * 8;
                size_t off = (size_t)r * N + c0;
                float v0 = acc[mi][ni][2 * h + 0];
                float v1 = acc[mi][ni][2 * h + 1];
                if (FUSE) {
                    v0 = xres[off]     + cs[c0]     * v0;
                    v1 = xres[off + 1] + cs[c0 + 1] * v1;
                }
                float2 st; st.x = v0; st.y = v1;
                *(float2*)(C + off) = st;
            }
        }
    }
}

// ---------------- prep: weights -> fp16, 64-wide k-permute ---------------
// Thread handles one 32-k half-group (contiguous src), writes 32 permuted
// fp16 (contiguous dst: chunks 4sp..4sp+3 of its 64-group).
template<size_t TOTAL>
__global__ void round_perm_k(const float* __restrict__ src, __half* __restrict__ dst) {
    size_t i = (size_t)blockIdx.x * blockDim.x + threadIdx.x;
    if (i >= TOTAL / 32) return;
    const float* s = src + 32 * i;
    float v[32];
    #pragma unroll
    for (int q = 0; q < 8; q++) {
        float4 f = ((const float4*)s)[q];
        v[4*q] = f.x; v[4*q+1] = f.y; v[4*q+2] = f.z; v[4*q+3] = f.w;
    }
    uint4* d4 = (uint4*)(dst + 32 * i);
    #pragma unroll
    for (int t = 0; t < 4; t++) {
        uint4 o;
        o.x = pk(v[2*t],      v[2*t + 1]);
        o.y = pk(v[2*t + 8],  v[2*t + 9]);
        o.z = pk(v[2*t + 16], v[2*t + 17]);
        o.w = pk(v[2*t + 24], v[2*t + 25]);
        d4[t] = o;
    }
}

// ---------------- rmsnorm (emits fp16, 64-perm rows) ---------------------
__global__ void __launch_bounds__(256) rmsnorm_k(const float* __restrict__ x) {
    int row = blockIdx.x;
    const float* xr = x + (size_t)row * DIMD;
    int t = threadIdx.x;
    int g = t >> 3, c = t & 7, sp = (c >> 2) & 1, tt = c & 3;
    int k0 = 64 * g + 32 * sp + 2 * tt;

    float2 p0 = *(const float2*)(xr + k0);
    float2 p1 = *(const float2*)(xr + k0 + 8);
    float2 p2 = *(const float2*)(xr + k0 + 16);
    float2 p3 = *(const float2*)(xr + k0 + 24);
    float ss = p0.x*p0.x + p0.y*p0.y + p1.x*p1.x + p1.y*p1.y
             + p2.x*p2.x + p2.y*p2.y + p3.x*p3.x + p3.y*p3.y;
    #pragma unroll
    for (int off = 16; off > 0; off >>= 1)
        ss += __shfl_xor_sync(0xffffffffu, ss, off);

    __shared__ float red[8];
    __shared__ float sscale;
    int warp = t >> 5, lane = t & 31;
    if (lane == 0) red[warp] = ss;
    __syncthreads();
    if (t == 0) {
        float tot = 0.f;
        #pragma unroll
        for (int i = 0; i < 8; i++) tot += red[i];
        sscale = rsqrtf(tot * (1.0f / DIMD) + 1.1920928955078125e-07f);
    }
    __syncthreads();
    float sc = sscale;

    uint4 st;
    st.x = pk(p0.x * sc, p0.y * sc);
    st.y = pk(p1.x * sc, p1.y * sc);
    st.z = pk(p2.x * sc, p2.y * sc);
    st.w = pk(p3.x * sc, p3.y * sc);
    *(uint4*)(g_xn + (size_t)row * DIMD + 64 * g + 8 * c) = st;
}

// ---------------- gate * causal dwconv * gate (fp16, 64-perm o) ----------
__global__ void __launch_bounds__(256) gateconv_k(const float* __restrict__ cw,
                                                  const float* __restrict__ cb,
                                                  const int* __restrict__ dil_p) {
    int dil = *dil_p;
    size_t idx = (size_t)blockIdx.x * blockDim.x + threadIdx.x;
    if (idx >= (size_t)MTOT * 256) return;
    int c = (int)(idx & 255);
    int m = (int)(idx >> 8);
    int s = m % SEQ;
    int g = c >> 3, cc = c & 7, sp = (cc >> 2) & 1, tt = cc & 3;
    int d0 = 64 * g + 32 * sp + 2 * tt;

    const float* hr  = g_h + (size_t)m * N1;
    const float* hp1 = hr - (size_t)dil * N1;
    const float* hp2 = hr - (size_t)(2 * dil) * N1;
    bool ok1 = (s >= dil), ok2 = (s >= 2 * dil);

    uint32_t outw[4];
    #pragma unroll
    for (int p = 0; p < 4; p++) {
        int d = d0 + p * 8;
        float w0a = cw[3*d],   w1a = cw[3*d+1], w2a = cw[3*d+2];
        float w0b = cw[3*d+3], w1b = cw[3*d+4], w2b = cw[3*d+5];
        float2 B0 = *(const float2*)(hr + d);
        float2 Z0 = *(const float2*)(hr + 2 * DIMD + d);
        float a0 = cb[d]     + w2a * (B0.x * Z0.x);
        float a1 = cb[d + 1] + w2b * (B0.y * Z0.y);
        if (ok1) {
            float2 B1 = *(const float2*)(hp1 + d);
            float2 Z1 = *(const float2*)(hp1 + 2 * DIMD + d);
            a0 += w1a * (B1.x * Z1.x);
            a1 += w1b * (B1.y * Z1.y);
        }
        if (ok2) {
            float2 B2 = *(const float2*)(hp2 + d);
            float2 Z2 = *(const float2*)(hp2 + 2 * DIMD + d);
            a0 += w0a * (B2.x * Z2.x);
            a1 += w0b * (B2.y * Z2.y);
        }
        float2 Cg = *(const float2*)(hr + DIMD + d);
        outw[p] = pk(Cg.x * a0, Cg.y * a1);
    }
    uint4 st; st.x = outw[0]; st.y = outw[1]; st.z = outw[2]; st.w = outw[3];
    *(uint4*)(g_o + (size_t)m * DIMD + 64 * g + 8 * cc) = st;
}

// ---------------- launch ----------------
extern "C" void kernel_launch(void* const* d_in, const int* in_sizes, int n_in,
                              void* d_out, int out_size) {
    const float* x   = (const float*)d_in[0];
    const float* We  = (const float*)d_in[1];
    const float* cw  = (const float*)d_in[2];
    const float* cb  = (const float*)d_in[3];
    const float* Wp  = (const float*)d_in[4];
    const float* cs  = (const float*)d_in[5];
    const int*   dil = (const int*)  d_in[6];
    float* out = (float*)d_out;

    __half *p_xn, *p_o, *p_We, *p_Wp;
    float *p_h;
    cudaGetSymbolAddress((void**)&p_xn, g_xn);
    cudaGetSymbolAddress((void**)&p_h,  g_h);
    cudaGetSymbolAddress((void**)&p_o,  g_o);
    cudaGetSymbolAddress((void**)&p_We, g_We);
    cudaGetSymbolAddress((void**)&p_Wp, g_Wp);

    cudaFuncSetAttribute(gemm_k<N1, false>, cudaFuncAttributeMaxDynamicSharedMemorySize, SMEM_SZ);
    cudaFuncSetAttribute(gemm_k<KD, true >, cudaFuncAttributeMaxDynamicSharedMemorySize, SMEM_SZ);

    {
        constexpr size_t TWE = (size_t)N1 * KD;
        constexpr size_t TWP = (size_t)KD * KD;
        round_perm_k<TWE><<<(unsigned)((TWE / 32 + 255) / 256), 256>>>(We, p_We);
        round_perm_k<TWP><<<(unsigned)((TWP / 32 + 255) / 256), 256>>>(Wp, p_Wp);
    }

    rmsnorm_k<<<MTOT, 256>>>(x);

    // h = xn @ We^T   [16384 x 6144]
    gemm_k<N1, false><<<dim3(N1 / BN, MTOT / BM), 256, SMEM_SZ>>>(p_xn, p_We, p_h, nullptr, nullptr);

    {
        size_t n = (size_t)MTOT * 256;
        gateconv_k<<<(unsigned)((n + 255) / 256), 256>>>(cw, cb, dil);
    }

    // out = x + cs * (o @ Wp^T)   [16384 x 2048]
    gemm_k<KD, true><<<dim3(KD / BN, MTOT / BM), 256, SMEM_SZ>>>(p_o, p_Wp, out, x, cs);
}

// round 15
// speedup vs baseline: 2.4874x; 1.0388x over previous
#include <cuda_runtime.h>
#include <cuda_fp16.h>
#include <cstdint>
#include <cstddef>

// ---------------- problem constants ----------------
#define DIMD   2048
#define MTOT   16384            // 4*4096 tokens
#define N1     6144             // 3*DIMD
#define KD     2048
#define SEQ    4096

// ---------------- scratch ----------------
// GEMM operands in fp16 with 64-wide k-permutation (see v14). g_h now fp16.
__device__ __half g_xn[(size_t)MTOT * KD];
__device__ __half g_h [(size_t)MTOT * N1];
__device__ __half g_o [(size_t)MTOT * KD];
__device__ __half g_We[(size_t)N1  * KD];
__device__ __half g_Wp[(size_t)KD  * KD];

// ---------------- helpers ----------------
__device__ __forceinline__ uint32_t pk(float a, float b) {
    __half2 h = __floats2half2_rn(a, b);
    return *reinterpret_cast<uint32_t*>(&h);
}
__device__ __forceinline__ void cpasync16(void* smem, const void* gmem) {
    uint32_t s = (uint32_t)__cvta_generic_to_shared(smem);
    asm volatile("cp.async.cg.shared.global [%0], [%1], 16;" :: "r"(s), "l"(gmem));
}
#define CP_COMMIT() asm volatile("cp.async.commit_group;")
#define CP_WAIT2()  asm volatile("cp.async.wait_group 2;")

__device__ __forceinline__ uint4 lds128(uint32_t a) {
    uint4 v;
    asm volatile("ld.shared.v4.b32 {%0,%1,%2,%3}, [%4];"
                 : "=r"(v.x), "=r"(v.y), "=r"(v.z), "=r"(v.w) : "r"(a));
    return v;
}

__device__ __forceinline__ void mma_f16(float c[4], uint32_t a0, uint32_t a1,
                                        uint32_t a2, uint32_t a3,
                                        uint32_t b0, uint32_t b1) {
    asm volatile(
        "mma.sync.aligned.m16n8k16.row.col.f32.f16.f16.f32 "
        "{%0,%1,%2,%3}, {%4,%5,%6,%7}, {%8,%9}, {%0,%1,%2,%3};"
        : "+f"(c[0]), "+f"(c[1]), "+f"(c[2]), "+f"(c[3])
        : "r"(a0), "r"(a1), "r"(a2), "r"(a3), "r"(b0), "r"(b1));
}

// ---------------- fp16 GEMM v15: C[M,N] = A[M,K] * B[N,K]^T ---------------
// Same mainloop as v14 (CTA 128x256, 8 warps, warp 64x64, BK=64 fp16,
// NSTG=4, conflict-free XOR-swizzled LDS.128, fb ping-pong + fa reload).
// Epilogue: HOUT=true stores half2 (for g_h), else float2 with fused residual.
constexpr int BM = 128, BN = 256, NSTG = 4;
constexpr int BKH = 64;                              // halves per k-tile
constexpr int ROW_H = 64;                            // halves per smem row (128B)
constexpr int A_HALVES = BM * ROW_H;                 // 8192
constexpr int B_HALVES = BN * ROW_H;                 // 16384
constexpr int STG_HALVES = A_HALVES + B_HALVES;      // 24576
constexpr int STG_BYTES  = STG_HALVES * 2;           // 49152
constexpr int SMEM_SZ = NSTG * STG_BYTES;            // 196608 B

template<int N, bool HOUT>
__global__ void __launch_bounds__(256, 1) gemm_k(const __half* __restrict__ A,
                                                 const __half* __restrict__ B,
                                                 void* __restrict__ Cout,
                                                 const float* __restrict__ xres,
                                                 const float* __restrict__ cs) {
    constexpr int K = KD;
    constexpr int KT = K / BKH;   // 32
    extern __shared__ __half smem[];
    const uint32_t sbase = (uint32_t)__cvta_generic_to_shared(smem);

    const int bm = blockIdx.y * BM;
    const int bn = blockIdx.x * BN;
    const int tid  = threadIdx.x;
    const int warp = tid >> 5, lane = tid & 31;
    const int wm = (warp & 1) * 64;
    const int wn = (warp >> 1) * 64;
    const int gid = lane >> 2, tig = lane & 3;

    float acc[4][8][4];
    #pragma unroll
    for (int mi = 0; mi < 4; mi++)
        #pragma unroll
        for (int ni = 0; ni < 8; ni++)
            #pragma unroll
            for (int r = 0; r < 4; r++) acc[mi][ni][r] = 0.f;

    const __half* Abase = A + (size_t)bm * K;
    const __half* Bbase = B + (size_t)bn * K;

    auto load_stage = [&](int kt) {
        __half* sa = smem + (kt % NSTG) * STG_HALVES;
        __half* sb = sa + A_HALVES;
        const __half* Ag = Abase + kt * BKH;
        const __half* Bg = Bbase + kt * BKH;
        #pragma unroll
        for (int i = 0; i < 4; i++) {           // A: 1024 chunks, 4/thread
            int c = tid + i * 256;
            int row = c >> 3, ck = c & 7;
            int key = ((row & 1) << 2) | ((row >> 1) & 3);
            cpasync16(sa + row * ROW_H + ((ck ^ key) << 3),
                      Ag + (size_t)row * K + ck * 8);
        }
        #pragma unroll
        for (int i = 0; i < 8; i++) {           // B: 2048 chunks, 8/thread
            int c = tid + i * 256;
            int row = c >> 3, ck = c & 7;
            int key = ((row & 1) << 2) | ((row >> 1) & 3);
            cpasync16(sb + row * ROW_H + ((ck ^ key) << 3),
                      Bg + (size_t)row * K + ck * 8);
        }
    };

    uint4 fa[4][2];   // [mi][row-half]; one super-step (2 k16-steps)
    uint4 fb0[4];     // ni 0..3
    uint4 fb1[4];     // ni 4..7

    const uint32_t key = (uint32_t)(((gid & 1) << 2) | ((gid >> 1) & 3));
    const uint32_t col0 = (uint32_t)((tig ^ key) << 4);
    const uint32_t col1 = (uint32_t)(((4 | tig) ^ key) << 4);
    const uint32_t arow = (uint32_t)(wm + gid) * 128;
    const uint32_t brow = (uint32_t)(A_HALVES * 2) + (uint32_t)(wn + gid) * 128;

    auto ldfa = [&](int mi, uint32_t base) {
        fa[mi][0] = lds128(base + (uint32_t)(mi * 2048));
        fa[mi][1] = lds128(base + (uint32_t)(mi * 2048 + 1024));
    };
    auto mma_g = [&](int mi, const uint4* fb, int nib) {
        #pragma unroll
        for (int j = 0; j < 4; j++) {
            int ni = nib + j;
            mma_f16(acc[mi][ni], fa[mi][0].x, fa[mi][1].x,
                                fa[mi][0].y, fa[mi][1].y, fb[j].x, fb[j].y);
            mma_f16(acc[mi][ni], fa[mi][0].z, fa[mi][1].z,
                                fa[mi][0].w, fa[mi][1].w, fb[j].z, fb[j].w);
        }
    };

    load_stage(0); CP_COMMIT();
    load_stage(1); CP_COMMIT();
    load_stage(2); CP_COMMIT();
    CP_WAIT2();
    __syncthreads();
    {
        const uint32_t aB = sbase + arow + col0;
        const uint32_t bB = sbase + brow + col0;
        #pragma unroll
        for (int mi = 0; mi < 4; mi++) ldfa(mi, aB);
        #pragma unroll
        for (int j = 0; j < 4; j++) fb0[j] = lds128(bB + (uint32_t)(j * 1024));
    }

    #pragma unroll 1
    for (int kt = 0; kt < KT; kt++) {
        const uint32_t stg = sbase + (uint32_t)(kt % NSTG) * STG_BYTES;
        const uint32_t aS = stg + arow;
        const uint32_t bS = stg + brow;

        #pragma unroll
        for (int mi = 0; mi < 4; mi++) {
            fb1[mi] = lds128(bS + col0 + (uint32_t)((4 + mi) * 1024));
            mma_g(mi, fb0, 0);
        }
        if (kt + 3 < KT) load_stage(kt + 3);
        CP_COMMIT();
        #pragma unroll
        for (int mi = 0; mi < 4; mi++) {
            mma_g(mi, fb1, 4);
            ldfa(mi, aS + col1);
            fb0[mi] = lds128(bS + col1 + (uint32_t)(mi * 1024));
        }

        #pragma unroll
        for (int mi = 0; mi < 4; mi++) {
            fb1[mi] = lds128(bS + col1 + (uint32_t)((4 + mi) * 1024));
            mma_g(mi, fb0, 0);
        }
        if (kt + 1 < KT) {
            CP_WAIT2();
            __syncthreads();
            const uint32_t nstg = sbase + (uint32_t)((kt + 1) % NSTG) * STG_BYTES;
            const uint32_t naS = nstg + arow + col0;
            const uint32_t nbS = nstg + brow + col0;
            #pragma unroll
            for (int mi = 0; mi < 4; mi++) {
                mma_g(mi, fb1, 4);
                ldfa(mi, naS);
                fb0[mi] = lds128(nbS + (uint32_t)(mi * 1024));
            }
        } else {
            #pragma unroll
            for (int mi = 0; mi < 4; mi++) mma_g(mi, fb1, 4);
        }
    }

    // epilogue
    #pragma unroll
    for (int mi = 0; mi < 4; mi++) {
        #pragma unroll
        for (int ni = 0; ni < 8; ni++) {
            int r0 = bm + wm + mi * 16 + gid;
            int c0 = bn + wn + ni * 8 + tig * 2;
            #pragma unroll
            for (int h = 0; h < 2; h++) {
                int r = r0 + h * 8;
                size_t off = (size_t)r * N + c0;
                float v0 = acc[mi][ni][2 * h + 0];
                float v1 = acc[mi][ni][2 * h + 1];
                if (HOUT) {
                    *(uint32_t*)((__half*)Cout + off) = pk(v0, v1);
                } else {
                    v0 = xres[off]     + cs[c0]     * v0;
                    v1 = xres[off + 1] + cs[c0 + 1] * v1;
                    float2 st; st.x = v0; st.y = v1;
                    *(float2*)((float*)Cout + off) = st;
                }
            }
        }
    }
}

// ---------------- prep: weights -> fp16, 64-wide k-permute ---------------
template<size_t TOTAL>
__global__ void round_perm_k(const float* __restrict__ src, __half* __restrict__ dst) {
    size_t i = (size_t)blockIdx.x * blockDim.x + threadIdx.x;
    if (i >= TOTAL / 32) return;
    const float* s = src + 32 * i;
    float v[32];
    #pragma unroll
    for (int q = 0; q < 8; q++) {
        float4 f = ((const float4*)s)[q];
        v[4*q] = f.x; v[4*q+1] = f.y; v[4*q+2] = f.z; v[4*q+3] = f.w;
    }
    uint4* d4 = (uint4*)(dst + 32 * i);
    #pragma unroll
    for (int t = 0; t < 4; t++) {
        uint4 o;
        o.x = pk(v[2*t],      v[2*t + 1]);
        o.y = pk(v[2*t + 8],  v[2*t + 9]);
        o.z = pk(v[2*t + 16], v[2*t + 17]);
        o.w = pk(v[2*t + 24], v[2*t + 25]);
        d4[t] = o;
    }
}

// ---------------- rmsnorm (emits fp16, 64-perm rows) ---------------------
__global__ void __launch_bounds__(256) rmsnorm_k(const float* __restrict__ x) {
    int row = blockIdx.x;
    const float* xr = x + (size_t)row * DIMD;
    int t = threadIdx.x;
    int g = t >> 3, c = t & 7, sp = (c >> 2) & 1, tt = c & 3;
    int k0 = 64 * g + 32 * sp + 2 * tt;

    float2 p0 = *(const float2*)(xr + k0);
    float2 p1 = *(const float2*)(xr + k0 + 8);
    float2 p2 = *(const float2*)(xr + k0 + 16);
    float2 p3 = *(const float2*)(xr + k0 + 24);
    float ss = p0.x*p0.x + p0.y*p0.y + p1.x*p1.x + p1.y*p1.y
             + p2.x*p2.x + p2.y*p2.y + p3.x*p3.x + p3.y*p3.y;
    #pragma unroll
    for (int off = 16; off > 0; off >>= 1)
        ss += __shfl_xor_sync(0xffffffffu, ss, off);

    __shared__ float red[8];
    __shared__ float sscale;
    int warp = t >> 5, lane = t & 31;
    if (lane == 0) red[warp] = ss;
    __syncthreads();
    if (t == 0) {
        float tot = 0.f;
        #pragma unroll
        for (int i = 0; i < 8; i++) tot += red[i];
        sscale = rsqrtf(tot * (1.0f / DIMD) + 1.1920928955078125e-07f);
    }
    __syncthreads();
    float sc = sscale;

    uint4 st;
    st.x = pk(p0.x * sc, p0.y * sc);
    st.y = pk(p1.x * sc, p1.y * sc);
    st.z = pk(p2.x * sc, p2.y * sc);
    st.w = pk(p3.x * sc, p3.y * sc);
    *(uint4*)(g_xn + (size_t)row * DIMD + 64 * g + 8 * c) = st;
}

// ---------------- gate * causal dwconv * gate (fp16 h in, fp16 perm o out)
__global__ void __launch_bounds__(256) gateconv_k(const float* __restrict__ cw,
                                                  const float* __restrict__ cb,
                                                  const int* __restrict__ dil_p) {
    int dil = *dil_p;
    size_t idx = (size_t)blockIdx.x * blockDim.x + threadIdx.x;
    if (idx >= (size_t)MTOT * 256) return;
    int c = (int)(idx & 255);
    int m = (int)(idx >> 8);
    int s = m % SEQ;
    int g = c >> 3, cc = c & 7, sp = (cc >> 2) & 1, tt = cc & 3;
    int d0 = 64 * g + 32 * sp + 2 * tt;

    const __half* hr  = g_h + (size_t)m * N1;
    const __half* hp1 = hr - (size_t)dil * N1;
    const __half* hp2 = hr - (size_t)(2 * dil) * N1;
    bool ok1 = (s >= dil), ok2 = (s >= 2 * dil);

    uint32_t outw[4];
    #pragma unroll
    for (int p = 0; p < 4; p++) {
        int d = d0 + p * 8;
        float w0a = cw[3*d],   w1a = cw[3*d+1], w2a = cw[3*d+2];
        float w0b = cw[3*d+3], w1b = cw[3*d+4], w2b = cw[3*d+5];
        float2 B0 = __half22float2(*(const __half2*)(hr + d));
        float2 Z0 = __half22float2(*(const __half2*)(hr + 2 * DIMD + d));
        float a0 = cb[d]     + w2a * (B0.x * Z0.x);
        float a1 = cb[d + 1] + w2b * (B0.y * Z0.y);
        if (ok1) {
            float2 B1 = __half22float2(*(const __half2*)(hp1 + d));
            float2 Z1 = __half22float2(*(const __half2*)(hp1 + 2 * DIMD + d));
            a0 += w1a * (B1.x * Z1.x);
            a1 += w1b * (B1.y * Z1.y);
        }
        if (ok2) {
            float2 B2 = __half22float2(*(const __half2*)(hp2 + d));
            float2 Z2 = __half22float2(*(const __half2*)(hp2 + 2 * DIMD + d));
            a0 += w0a * (B2.x * Z2.x);
            a1 += w0b * (B2.y * Z2.y);
        }
        float2 Cg = __half22float2(*(const __half2*)(hr + DIMD + d));
        outw[p] = pk(Cg.x * a0, Cg.y * a1);
    }
    uint4 st; st.x = outw[0]; st.y = outw[1]; st.z = outw[2]; st.w = outw[3];
    *(uint4*)(g_o + (size_t)m * DIMD + 64 * g + 8 * cc) = st;
}

// ---------------- launch ----------------
extern "C" void kernel_launch(void* const* d_in, const int* in_sizes, int n_in,
                              void* d_out, int out_size) {
    const float* x   = (const float*)d_in[0];
    const float* We  = (const float*)d_in[1];
    const float* cw  = (const float*)d_in[2];
    const float* cb  = (const float*)d_in[3];
    const float* Wp  = (const float*)d_in[4];
    const float* cs  = (const float*)d_in[5];
    const int*   dil = (const int*)  d_in[6];
    float* out = (float*)d_out;

    __half *p_xn, *p_h, *p_o, *p_We, *p_Wp;
    cudaGetSymbolAddress((void**)&p_xn, g_xn);
    cudaGetSymbolAddress((void**)&p_h,  g_h);
    cudaGetSymbolAddress((void**)&p_o,  g_o);
    cudaGetSymbolAddress((void**)&p_We, g_We);
    cudaGetSymbolAddress((void**)&p_Wp, g_Wp);

    cudaFuncSetAttribute(gemm_k<N1, true >, cudaFuncAttributeMaxDynamicSharedMemorySize, SMEM_SZ);
    cudaFuncSetAttribute(gemm_k<KD, false>, cudaFuncAttributeMaxDynamicSharedMemorySize, SMEM_SZ);

    {
        constexpr size_t TWE = (size_t)N1 * KD;
        constexpr size_t TWP = (size_t)KD * KD;
        round_perm_k<TWE><<<(unsigned)((TWE / 32 + 255) / 256), 256>>>(We, p_We);
        round_perm_k<TWP><<<(unsigned)((TWP / 32 + 255) / 256), 256>>>(Wp, p_Wp);
    }

    rmsnorm_k<<<MTOT, 256>>>(x);

    // h = xn @ We^T   [16384 x 6144]  (fp16 out)
    gemm_k<N1, true><<<dim3(N1 / BN, MTOT / BM), 256, SMEM_SZ>>>(p_xn, p_We, p_h, nullptr, nullptr);

    {
        size_t n = (size_t)MTOT * 256;
        gateconv_k<<<(unsigned)((n + 255) / 256), 256>>>(cw, cb, dil);
    }

    // out = x + cs * (o @ Wp^T)   [16384 x 2048]  (f32 out, fused residual)
    gemm_k<KD, false><<<dim3(KD / BN, MTOT / BM), 256, SMEM_SZ>>>(p_o, p_Wp, out, x, cs);
}